// round 14
// baseline (speedup 1.0000x reference)
#include <cuda_runtime.h>
#include <cuda_fp16.h>
#include <math.h>
#include <stdint.h>

// Problem constants
#define BB    2048
#define DD    512
#define GG    2048
#define TSRC  32
#define TTGT  32
#define DTGT  80
#define DSRC  100
#define NL    2

// GEMM tiling
#define CTA_M 128
#define CTA_N 128
#define NSTAGE 3
#define NROWB (BB / CTA_M)    // 16

#define STAGE_BYTES 32768
#define OFF_A0 0
#define OFF_A1 8192
#define OFF_B0 16384
#define OFF_B1 24576
#define BIAS_OFF (NSTAGE * STAGE_BYTES)          // 98304
#define SMEM_TOTAL_GEMM (BIAS_OFF + CTA_N * 4)   // 98816
#define SMEM_LOGITS (DTGT * DD * 4)              // 163840

#define SWZ(x) ((uint32_t)(x) ^ ((((uint32_t)(x)) >> 3) & 0x70))

typedef __half fp16;

// ---------------- persistent scratch ----------------
__device__ __align__(256) fp16 g_Xs0[(size_t)TSRC * BB * DD];
__device__ __align__(256) fp16 g_Xs1[(size_t)TSRC * BB * DD];
// permuted+split weights: [0]=encWhh0 [1]=encWih1 [2]=encWhh1 [3]=decWhh0 [4]=decWih1 [5]=decWhh1
__device__ __align__(256) fp16 g_Wp0[6][(size_t)GG * DD];
__device__ __align__(256) fp16 g_Wp1[6][(size_t)GG * DD];
__device__ __align__(256) fp16 g_hp0[NL][2][(size_t)BB * DD];
__device__ __align__(256) fp16 g_hp1[NL][2][(size_t)BB * DD];
__device__ float g_c[NL][(size_t)BB * DD];
__device__ float g_hf[(size_t)BB * DD];
__device__ float g_encT[(size_t)DSRC * GG];
__device__ float g_decT[(size_t)DTGT * GG];
__device__ float g_biasE[GG];
__device__ float g_biasD[GG];
__device__ int   g_pred[BB];

// ---------------- arg struct for runtime-dispatch GEMM ----------------
struct GArgs {
    const fp16 *A10, *A11, *W10, *W11;   // pass-0 operands
    const fp16 *A20, *A21, *W20, *W21;   // pass-1 operands
    const float* tb;                      // table (use_table) or permuted bias
    const int* tok; int tok_stride, tok_off;
    float* cst; float* hf;
    fp16 *h0o, *h1o, *x0o, *x1o;
    int npass; int use_table;
};

// ---------------- PTX helpers ----------------
__device__ __forceinline__ uint32_t smem_u32(const void* p) {
    uint32_t a;
    asm("{ .reg .u64 t; cvta.to.shared.u64 t, %1; cvt.u32.u64 %0, t; }" : "=r"(a) : "l"(p));
    return a;
}
__device__ __forceinline__ void cpasync16(uint32_t dst, const void* src) {
    asm volatile("cp.async.cg.shared.global [%0], [%1], 16;" :: "r"(dst), "l"(src));
}
#define CP_COMMIT()  asm volatile("cp.async.commit_group;" ::: "memory")
#define CP_WAIT(n)   asm volatile("cp.async.wait_group %0;" :: "n"(n) : "memory")

__device__ __forceinline__ void ldsm4(uint32_t* d, uint32_t addr) {
    asm volatile("ldmatrix.sync.aligned.m8n8.x4.shared.b16 {%0,%1,%2,%3}, [%4];"
        : "=r"(d[0]), "=r"(d[1]), "=r"(d[2]), "=r"(d[3]) : "r"(addr));
}
__device__ __forceinline__ void mma16816(float* c, const uint32_t* a, const uint32_t* b) {
    asm volatile(
        "mma.sync.aligned.m16n8k16.row.col.f32.f16.f16.f32 "
        "{%0,%1,%2,%3},{%4,%5,%6,%7},{%8,%9},{%0,%1,%2,%3};"
        : "+f"(c[0]), "+f"(c[1]), "+f"(c[2]), "+f"(c[3])
        : "r"(a[0]), "r"(a[1]), "r"(a[2]), "r"(a[3]), "r"(b[0]), "r"(b[1]));
}

__device__ __forceinline__ void split2(float x, fp16& a0, fp16& a1) {
    a0 = __float2half_rn(x);
    a1 = __float2half_rn(x - __half2float(a0));
}
__device__ __forceinline__ float sigf(float x) { return 1.f / (1.f + expf(-x)); }

// ---- fused GEMM + LSTM cell, runtime npass/use_table, grid.z dispatch ----
// (BYTE-IDENTICAL to the verified 9.39ms version — do not touch)
__global__ __launch_bounds__(256, 2)
void gemm_cell_dyn(GArgs a0, GArgs a1)
{
    const GArgs& a = (blockIdx.z == 1) ? a1 : a0;
    extern __shared__ char smem[];
    const uint32_t sb = smem_u32(smem);
    const int tid  = threadIdx.x;
    const int wid  = tid >> 5;
    const int lane = tid & 31;
    const int row0 = blockIdx.y * CTA_M;
    const int col0 = blockIdx.x * CTA_N;
    const int warp_m = (wid & 3) * 32;
    const int warp_n = (wid >> 2) * 64;
    const int KSTEPS = a.npass * 16;

    if (!a.use_table && tid < CTA_N)
        ((float*)(smem + BIAS_OFF))[tid] = a.tb[col0 + tid];

    auto load_stage = [&](int s, int slot) {
        const int pass = s >> 4;
        const size_t k0b = (size_t)(s & 15) * 64;
        const char* srcs[4];
        srcs[0] = (const char*)(pass ? a.A20 : a.A10) + (size_t)row0 * (DD * 2) + k0b;
        srcs[1] = (const char*)(pass ? a.A21 : a.A11) + (size_t)row0 * (DD * 2) + k0b;
        srcs[2] = (const char*)(pass ? a.W20 : a.W10) + (size_t)col0 * (DD * 2) + k0b;
        srcs[3] = (const char*)(pass ? a.W21 : a.W11) + (size_t)col0 * (DD * 2) + k0b;
        const uint32_t base = sb + slot * STAGE_BYTES;
        #pragma unroll
        for (int tile = 0; tile < 4; tile++) {
            #pragma unroll
            for (int hh = 0; hh < 2; hh++) {
                int j = hh * 256 + tid;
                int r = j >> 2, u = j & 3;
                cpasync16(base + tile * 8192 + SWZ(r * 64 + u * 16),
                          srcs[tile] + (size_t)r * (DD * 2) + u * 16);
            }
        }
        CP_COMMIT();
    };

    float acc[2][8][4];
    #pragma unroll
    for (int i = 0; i < 2; i++)
        #pragma unroll
        for (int j = 0; j < 8; j++)
            #pragma unroll
            for (int k = 0; k < 4; k++) acc[i][j][k] = 0.f;

    const int laA = lane & 15;
    const int luA = lane >> 4;
    const int laB = (lane & 7) + ((lane >> 4) << 3);
    const int luB = (lane >> 3) & 1;

    if (KSTEPS > 0) {
        load_stage(0, 0);
        load_stage(1, 1);

        #pragma unroll 1
        for (int s = 0; s < KSTEPS; s++) {
            if (s + 2 < KSTEPS) load_stage(s + 2, (s + 2) % NSTAGE);
            else CP_COMMIT();
            CP_WAIT(2);
            __syncthreads();

            const uint32_t stg = sb + (s % NSTAGE) * STAGE_BYTES;
            #pragma unroll
            for (int kh = 0; kh < 2; kh++) {
                uint32_t A[2][2][4];
                #pragma unroll
                for (int am = 0; am < 2; am++) {
                    uint32_t off = SWZ((warp_m + am * 16 + laA) * 64 + kh * 32 + luA * 16);
                    ldsm4(A[0][am], stg + OFF_A0 + off);
                    ldsm4(A[1][am], stg + OFF_A1 + off);
                }
                #pragma unroll
                for (int g = 0; g < 4; g++) {
                    uint32_t Bf[2][4];
                    uint32_t offb = SWZ((warp_n + g * 16 + laB) * 64 + kh * 32 + luB * 16);
                    ldsm4(Bf[0], stg + OFF_B0 + offb);
                    ldsm4(Bf[1], stg + OFF_B1 + offb);
                    #pragma unroll
                    for (int am = 0; am < 2; am++)
                        #pragma unroll
                        for (int sub = 0; sub < 2; sub++) {
                            float* c = acc[am][g * 2 + sub];
                            mma16816(c, A[0][am], &Bf[0][sub * 2]);
                            mma16816(c, A[0][am], &Bf[1][sub * 2]);
                            mma16816(c, A[1][am], &Bf[0][sub * 2]);
                        }
                }
            }
            __syncthreads();
        }
    } else {
        __syncthreads();   // bias/table visibility for npass==0 path
    }

    // ---- fused LSTM cell epilogue ----
    const float* bias_s = (const float*)(smem + BIAS_OFF);
    const int q = lane & 3, r = lane >> 2;
    const int dbase = ((col0 + warp_n) >> 4) * 4 + q;
    #pragma unroll
    for (int am = 0; am < 2; am++) {
        #pragma unroll
        for (int half = 0; half < 2; half++) {
            const int m = row0 + warp_m + am * 16 + r + half * 8;
            const float* trow = nullptr;
            if (a.use_table) {
                int tv = a.tok[(size_t)m * a.tok_stride + a.tok_off];
                trow = a.tb + (size_t)tv * GG + col0 + warp_n + q * 2;
            }
            #pragma unroll
            for (int g16 = 0; g16 < 4; g16++) {
                float* aIF = acc[am][g16 * 2 + 0];
                float* aGO = acc[am][g16 * 2 + 1];
                float gi = aIF[half * 2 + 0], gf = aIF[half * 2 + 1];
                float gg = aGO[half * 2 + 0], go = aGO[half * 2 + 1];
                if (a.use_table) {
                    float2 t0 = *(const float2*)(trow + g16 * 16);
                    float2 t1 = *(const float2*)(trow + g16 * 16 + 8);
                    gi += t0.x; gf += t0.y; gg += t1.x; go += t1.y;
                } else {
                    int cb = warp_n + g16 * 16 + q * 2;
                    gi += bias_s[cb]; gf += bias_s[cb + 1];
                    gg += bias_s[cb + 8]; go += bias_s[cb + 9];
                }
                float I = sigf(gi), F = sigf(gf), G = tanhf(gg), O = sigf(go);
                int d = dbase + g16 * 4;
                size_t idx = (size_t)m * DD + d;
                float cn = F * a.cst[idx] + I * G;
                float hn = O * tanhf(cn);
                a.cst[idx] = cn;
                if (a.hf) a.hf[idx] = hn;
                fp16 v0, v1; split2(hn, v0, v1);
                a.h0o[idx] = v0; a.h1o[idx] = v1;
                if (a.x0o) { a.x0o[idx] = v0; a.x1o[idx] = v1; }
            }
        }
    }
}

// ---------------- encoder t=0 init ----------------
__global__ void enc0_init(const int* __restrict__ src, const float* __restrict__ encT,
                          float* __restrict__ cst0,
                          fp16* __restrict__ h0o, fp16* __restrict__ h1o,
                          fp16* __restrict__ x0o, fp16* __restrict__ x1o)
{
    int idx = blockIdx.x * 256 + threadIdx.x;
    if (idx >= BB * DD) return;
    int b = idx >> 9, d = idx & 511;
    int tok = src[b * TSRC + 0];
    const float* row = encT + (size_t)tok * GG;
    int cbase = ((d >> 2) << 4) + ((d & 3) << 1);
    float gi = row[cbase + 0];
    float gf = row[cbase + 1];
    float gg = row[cbase + 8];
    float go = row[cbase + 9];
    float I = sigf(gi), F = sigf(gf), G = tanhf(gg), O = sigf(go);
    float cn = F * 0.f + I * G;
    float hn = O * tanhf(cn);
    cst0[idx] = cn;
    fp16 v0, v1; split2(hn, v0, v1);
    h0o[idx] = v0; h1o[idx] = v1;
    x0o[idx] = v0; x1o[idx] = v1;
}

// ---------------- fused prep kernels ----------------
__global__ void permsplit_all(const float* w0, const float* w1, const float* w2,
                              const float* w3, const float* w4, const float* w5,
                              fp16* __restrict__ P0, fp16* __restrict__ P1)
{
    const float* srcs[6] = { w0, w1, w2, w3, w4, w5 };
    int mtx = blockIdx.y;
    size_t base = (size_t)mtx * GG * DD;
    size_t i = (size_t)blockIdx.x * 256 + threadIdx.x;
    if (i >= (size_t)GG * DD) return;
    int n = (int)(i >> 9), k = (int)(i & 511);
    int g = n >> 9, d = n & 511;
    int c = ((d >> 2) << 4) + ((d & 3) << 1) + ((g >> 1) << 3) + (g & 1);
    fp16 a0, a1;
    split2(srcs[mtx][i], a0, a1);
    size_t o = base + ((size_t)c << 9) + k;
    P0[o] = a0; P1[o] = a1;
}

__global__ void permbias_all(const float* e1, const float* e2,
                             const float* d1, const float* d2,
                             float* __restrict__ bE, float* __restrict__ bD)
{
    int n = blockIdx.x * 256 + threadIdx.x;
    if (n >= GG) return;
    int g = n >> 9, d = n & 511;
    int c = ((d >> 2) << 4) + ((d & 3) << 1) + ((g >> 1) << 3) + (g & 1);
    bE[c] = e1[n] + e2[n];
    bD[c] = d1[n] + d2[n];
}

__global__ void table_all(const float* __restrict__ eemb, const float* __restrict__ eW,
                          const float* __restrict__ eb1, const float* __restrict__ eb2,
                          const float* __restrict__ demb, const float* __restrict__ dW,
                          const float* __restrict__ db1, const float* __restrict__ db2,
                          float* __restrict__ eT, float* __restrict__ dT)
{
    __shared__ float es[DD];
    int v = blockIdx.x;
    bool enc = v < DSRC;
    int vv = enc ? v : v - DSRC;
    const float* emb = enc ? eemb : demb;
    const float* W   = enc ? eW : dW;
    const float* b1  = enc ? eb1 : db1;
    const float* b2  = enc ? eb2 : db2;
    float* T         = enc ? eT : dT;
    int c = blockIdx.y * 128 + threadIdx.x;
    for (int i = threadIdx.x; i < DD; i += 128) es[i] = emb[(size_t)vv * DD + i];
    __syncthreads();
    int d = ((c >> 4) << 2) + ((c >> 1) & 3);
    int g = (((c >> 3) & 1) << 1) + (c & 1);
    int n = g * 512 + d;
    const float* w = W + (size_t)n * DD;
    float acc = b1[n] + b2[n];
    #pragma unroll 8
    for (int k = 0; k < DD; k++) acc = fmaf(es[k], w[k], acc);
    T[(size_t)vv * GG + c] = acc;
}

// ---------------- smem-cached logits + argmax ----------------
// 128 blocks x 16 rows; post_W cached in 160KB smem (1 CTA/SM).
// Per-lane FMA order, shfl reduction order, and strict-> first-index argmax
// are bitwise identical to the previous logits kernel.
__global__ __launch_bounds__(256, 1)
void logits_smem(const float* __restrict__ h,
                 const float* __restrict__ W,
                 const float* __restrict__ bias,
                 float* __restrict__ out, int t,
                 int* __restrict__ pred)
{
    extern __shared__ float ws[];            // [80][512]
    const int tid = threadIdx.x, wid = tid >> 5, lane = tid & 31;

    // cooperative W fill: 10240 float4s / 256 threads = 40 iters
    {
        float4* ws4 = (float4*)ws;
        const float4* W4 = (const float4*)W;
        #pragma unroll
        for (int i = 0; i < (DTGT * DD / 4) / 256; i++)
            ws4[i * 256 + tid] = W4[i * 256 + tid];
    }
    __syncthreads();

    const int rbase = blockIdx.x * 16 + wid * 2;
    #pragma unroll
    for (int rr = 0; rr < 2; rr++) {
        const int b = rbase + rr;
        const float* hrow = h + (size_t)b * DD;
        float hreg[16];
        #pragma unroll
        for (int j = 0; j < 16; j++) hreg[j] = hrow[lane + 32 * j];

        float best = 0.f; int bi = 0;
        for (int n = 0; n < DTGT; n++) {
            const float* wrow = ws + n * DD;
            float acc = 0.f;
            #pragma unroll
            for (int j = 0; j < 16; j++)
                acc = fmaf(hreg[j], wrow[lane + 32 * j], acc);
            #pragma unroll
            for (int o = 16; o; o >>= 1) acc += __shfl_xor_sync(0xFFFFFFFFu, acc, o);
            if (lane == 0) {
                float v = acc + bias[n];
                out[(size_t)b * (TTGT * DTGT) + t * DTGT + n] = v;
                if (n == 0 || v > best) { best = v; bi = n; }
            }
        }
        if (lane == 0) pred[b] = bi;
    }
}

// ---------------- host orchestration ----------------
extern "C" void kernel_launch(void* const* d_in, const int* in_sizes, int n_in,
                              void* d_out, int out_size)
{
    const int*   src     = (const int*)  d_in[0];
    const int*   tgt     = (const int*)  d_in[1];
    const float* enc_emb = (const float*)d_in[2];
    const float* dec_emb = (const float*)d_in[3];
    const float* enc_Wih = (const float*)d_in[4];
    const float* enc_Whh = (const float*)d_in[5];
    const float* enc_bih = (const float*)d_in[6];
    const float* enc_bhh = (const float*)d_in[7];
    const float* dec_Wih = (const float*)d_in[8];
    const float* dec_Whh = (const float*)d_in[9];
    const float* dec_bih = (const float*)d_in[10];
    const float* dec_bhh = (const float*)d_in[11];
    const float* post_W  = (const float*)d_in[12];
    const float* post_b  = (const float*)d_in[13];
    float* out = (float*)d_out;

    cudaFuncSetAttribute(gemm_cell_dyn, cudaFuncAttributeMaxDynamicSharedMemorySize, SMEM_TOTAL_GEMM);
    cudaFuncSetAttribute(logits_smem,   cudaFuncAttributeMaxDynamicSharedMemorySize, SMEM_LOGITS);

    fp16 *Xs0, *Xs1, *Wp0, *Wp1, *hp0, *hp1;
    float *cst, *hf, *encT, *decT, *biasE, *biasD;
    int* pred;
    cudaGetSymbolAddress((void**)&Xs0, g_Xs0);
    cudaGetSymbolAddress((void**)&Xs1, g_Xs1);
    cudaGetSymbolAddress((void**)&Wp0, g_Wp0);
    cudaGetSymbolAddress((void**)&Wp1, g_Wp1);
    cudaGetSymbolAddress((void**)&hp0, g_hp0);
    cudaGetSymbolAddress((void**)&hp1, g_hp1);
    cudaGetSymbolAddress((void**)&cst, g_c);
    cudaGetSymbolAddress((void**)&hf,  g_hf);
    cudaGetSymbolAddress((void**)&encT, g_encT);
    cudaGetSymbolAddress((void**)&decT, g_decT);
    cudaGetSymbolAddress((void**)&biasE, g_biasE);
    cudaGetSymbolAddress((void**)&biasD, g_biasD);
    cudaGetSymbolAddress((void**)&pred, g_pred);

    const size_t WSL = (size_t)GG * DD;
    const size_t HB  = (size_t)BB * DD;

    // layer-1 c state must start at zero (layer-0 c fully written by enc0_init)
    cudaMemsetAsync(cst + HB, 0, HB * sizeof(float), 0);

    // prep (3 kernels)
    permsplit_all<<<dim3((unsigned)((WSL + 255) / 256), 6), 256>>>(
        enc_Whh, enc_Wih + WSL, enc_Whh + WSL, dec_Whh, dec_Wih + WSL, dec_Whh + WSL, Wp0, Wp1);
    permbias_all<<<(GG + 255) / 256, 256>>>(enc_bih + GG, enc_bhh + GG,
                                            dec_bih + GG, dec_bhh + GG, biasE, biasD);
    table_all<<<dim3(DSRC + DTGT, GG / 128), 128>>>(
        enc_emb, enc_Wih, enc_bih, enc_bhh, dec_emb, dec_Wih, dec_bih, dec_bhh, encT, decT);

    int p0 = 0, p1 = 0;

    // ---- encoder t=0 via elementwise init ----
    enc0_init<<<(BB * DD + 255) / 256, 256>>>(src, encT, cst,
        hp0 + (0 * 2 + 1) * HB, hp1 + (0 * 2 + 1) * HB, Xs0, Xs1);
    p0 = 1;

    auto mk_l0_enc = [&](int t) {
        GArgs a = {};
        a.A10 = hp0 + (0 * 2 + p0) * HB;  a.A11 = hp1 + (0 * 2 + p0) * HB;
        a.W10 = Wp0 + 0 * WSL;            a.W11 = Wp1 + 0 * WSL;
        a.tb = encT; a.tok = src; a.tok_stride = TSRC; a.tok_off = t;
        a.cst = cst + 0 * HB; a.hf = nullptr;
        a.h0o = hp0 + (0 * 2 + (p0 ^ 1)) * HB;  a.h1o = hp1 + (0 * 2 + (p0 ^ 1)) * HB;
        a.x0o = Xs0 + (size_t)t * HB;  a.x1o = Xs1 + (size_t)t * HB;
        a.npass = 1; a.use_table = 1;
        return a;
    };
    auto mk_l1_enc = [&](int t) {
        GArgs a = {};
        a.A10 = Xs0 + (size_t)t * HB;  a.A11 = Xs1 + (size_t)t * HB;
        a.W10 = Wp0 + 1 * WSL;         a.W11 = Wp1 + 1 * WSL;
        a.A20 = hp0 + (1 * 2 + p1) * HB;  a.A21 = hp1 + (1 * 2 + p1) * HB;
        a.W20 = Wp0 + 2 * WSL;            a.W21 = Wp1 + 2 * WSL;
        a.tb = biasE; a.tok = nullptr; a.tok_stride = 0; a.tok_off = 0;
        a.cst = cst + 1 * HB; a.hf = nullptr;
        a.h0o = hp0 + (1 * 2 + (p1 ^ 1)) * HB;  a.h1o = hp1 + (1 * 2 + (p1 ^ 1)) * HB;
        a.x0o = nullptr; a.x1o = nullptr;
        a.npass = (t == 0) ? 1 : 2; a.use_table = 0;
        return a;
    };
    auto mk_l0_dec0 = [&]() {   // decoder l0 at t=0 (tokens = tgt[:,0])
        GArgs a = {};
        a.A10 = hp0 + (0 * 2 + p0) * HB;  a.A11 = hp1 + (0 * 2 + p0) * HB;
        a.W10 = Wp0 + 3 * WSL;            a.W11 = Wp1 + 3 * WSL;
        a.tb = decT; a.tok = tgt; a.tok_stride = TTGT; a.tok_off = 0;
        a.cst = cst + 0 * HB; a.hf = nullptr;
        a.h0o = hp0 + (0 * 2 + (p0 ^ 1)) * HB;  a.h1o = hp1 + (0 * 2 + (p0 ^ 1)) * HB;
        a.x0o = nullptr; a.x1o = nullptr;
        a.npass = 1; a.use_table = 1;
        return a;
    };

    // ---- encoder: diagonal waves tau = 1..TSRC ----
    for (int tau = 1; tau <= TSRC; tau++) {
        if (tau < TSRC) {
            GArgs a0 = mk_l0_enc(tau);
            GArgs a1 = mk_l1_enc(tau - 1);
            gemm_cell_dyn<<<dim3(GG / CTA_N, NROWB, 2), 256, SMEM_TOTAL_GEMM>>>(a0, a1);
            p0 ^= 1; p1 ^= 1;
        } else {
            // final wave: enc l1[31]  +  dec l0[0]  (independent, z=2)
            GArgs a0 = mk_l1_enc(tau - 1);
            GArgs a1 = mk_l0_dec0();
            gemm_cell_dyn<<<dim3(GG / CTA_N, NROWB, 2), 256, SMEM_TOTAL_GEMM>>>(a0, a1);
            p1 ^= 1; p0 ^= 1;
        }
    }

    // ---- decoder ----
    const dim3 gg(GG / CTA_N, NROWB, 1);
    for (int t = 0; t < TTGT; t++) {
        if (t > 0) {
            // layer 0: h-GEMM + table gather (pred tokens)
            GArgs a = {};
            a.A10 = hp0 + (0 * 2 + p0) * HB;  a.A11 = hp1 + (0 * 2 + p0) * HB;
            a.W10 = Wp0 + 3 * WSL;            a.W11 = Wp1 + 3 * WSL;
            a.tb = decT;
            a.tok = pred;  a.tok_stride = 1;  a.tok_off = 0;
            a.cst = cst + 0 * HB; a.hf = nullptr;
            a.h0o = hp0 + (0 * 2 + (p0 ^ 1)) * HB;  a.h1o = hp1 + (0 * 2 + (p0 ^ 1)) * HB;
            a.x0o = nullptr; a.x1o = nullptr;
            a.npass = 1; a.use_table = 1;
            gemm_cell_dyn<<<gg, 256, SMEM_TOTAL_GEMM>>>(a, a);
            p0 ^= 1;
        }
        // layer 1: dual GEMM (x = layer0 h of this step)
        GArgs b = {};
        b.A10 = hp0 + (0 * 2 + p0) * HB;  b.A11 = hp1 + (0 * 2 + p0) * HB;   // l0 output
        b.W10 = Wp0 + 4 * WSL;            b.W11 = Wp1 + 4 * WSL;
        b.A20 = hp0 + (1 * 2 + p1) * HB;  b.A21 = hp1 + (1 * 2 + p1) * HB;
        b.W20 = Wp0 + 5 * WSL;            b.W21 = Wp1 + 5 * WSL;
        b.tb = biasD; b.tok = nullptr; b.tok_stride = 0; b.tok_off = 0;
        b.cst = cst + 1 * HB; b.hf = hf;
        b.h0o = hp0 + (1 * 2 + (p1 ^ 1)) * HB;  b.h1o = hp1 + (1 * 2 + (p1 ^ 1)) * HB;
        b.x0o = nullptr; b.x1o = nullptr;
        b.npass = 2; b.use_table = 0;
        gemm_cell_dyn<<<gg, 256, SMEM_TOTAL_GEMM>>>(b, b);
        p1 ^= 1;

        logits_smem<<<BB / 16, 256, SMEM_LOGITS>>>(hf, post_W, post_b, out, t, pred);
    }
}

// round 15
// speedup vs baseline: 1.0303x; 1.0303x over previous
#include <cuda_runtime.h>
#include <cuda_fp16.h>
#include <math.h>
#include <stdint.h>

// Problem constants
#define BB    2048
#define DD    512
#define GG    2048
#define TSRC  32
#define TTGT  32
#define DTGT  80
#define DSRC  100
#define NL    2

// GEMM tiling
#define CTA_M 128
#define CTA_N 128
#define NSTAGE 3
#define NROWB (BB / CTA_M)    // 16

#define STAGE_BYTES 32768
#define OFF_A0 0
#define OFF_A1 8192
#define OFF_B0 16384
#define OFF_B1 24576
#define BIAS_OFF (NSTAGE * STAGE_BYTES)          // 98304
#define SMEM_TOTAL_GEMM (BIAS_OFF + CTA_N * 4)   // 98816
#define SMEM_STORE (NSTAGE * STAGE_BYTES)        // 98304

#define SWZ(x) ((uint32_t)(x) ^ ((((uint32_t)(x)) >> 3) & 0x70))

typedef __half fp16;

// ---------------- persistent scratch ----------------
__device__ __align__(256) fp16 g_Xs0[(size_t)TSRC * BB * DD];
__device__ __align__(256) fp16 g_Xs1[(size_t)TSRC * BB * DD];
// permuted+split weights: [0]=encWhh0 [1]=encWih1 [2]=encWhh1 [3]=decWhh0 [4]=decWih1 [5]=decWhh1
__device__ __align__(256) fp16 g_Wp0[6][(size_t)GG * DD];
__device__ __align__(256) fp16 g_Wp1[6][(size_t)GG * DD];
__device__ __align__(256) fp16 g_hp0[NL][2][(size_t)BB * DD];
__device__ __align__(256) fp16 g_hp1[NL][2][(size_t)BB * DD];
__device__ float g_c[NL][(size_t)BB * DD];
__device__ float g_hf[(size_t)BB * DD];
__device__ float g_gatesH[(size_t)BB * GG];
__device__ float g_encT[(size_t)DSRC * GG];
__device__ float g_decT[(size_t)DTGT * GG];
__device__ float g_biasE[GG];
__device__ float g_biasD[GG];
__device__ int   g_pred[BB];

// ---------------- arg structs ----------------
struct GArgs {
    const fp16 *A10, *A11, *W10, *W11;   // pass-0 operands
    const fp16 *A20, *A21, *W20, *W21;   // pass-1 operands
    const float* tb;                      // table (use_table) or permuted bias
    const int* tok; int tok_stride, tok_off;
    float* cst; float* hf;
    fp16 *h0o, *h1o, *x0o, *x1o;
    int npass; int use_table;
};

struct DCArgs {                           // dec_fused cell role (table+cell)
    const fp16 *A0, *A1, *W0, *W1;
    const float* tb;
    const int* tok; int tok_stride, tok_off;
    float* cst;
    fp16 *h0o, *h1o;
};
struct DSArgs {                           // dec_fused store role
    const fp16 *A0, *A1, *W0, *W1;
    float* gates;
};

// ---------------- PTX helpers ----------------
__device__ __forceinline__ uint32_t smem_u32(const void* p) {
    uint32_t a;
    asm("{ .reg .u64 t; cvta.to.shared.u64 t, %1; cvt.u32.u64 %0, t; }" : "=r"(a) : "l"(p));
    return a;
}
__device__ __forceinline__ void cpasync16(uint32_t dst, const void* src) {
    asm volatile("cp.async.cg.shared.global [%0], [%1], 16;" :: "r"(dst), "l"(src));
}
#define CP_COMMIT()  asm volatile("cp.async.commit_group;" ::: "memory")
#define CP_WAIT(n)   asm volatile("cp.async.wait_group %0;" :: "n"(n) : "memory")

__device__ __forceinline__ void ldsm4(uint32_t* d, uint32_t addr) {
    asm volatile("ldmatrix.sync.aligned.m8n8.x4.shared.b16 {%0,%1,%2,%3}, [%4];"
        : "=r"(d[0]), "=r"(d[1]), "=r"(d[2]), "=r"(d[3]) : "r"(addr));
}
__device__ __forceinline__ void mma16816(float* c, const uint32_t* a, const uint32_t* b) {
    asm volatile(
        "mma.sync.aligned.m16n8k16.row.col.f32.f16.f16.f32 "
        "{%0,%1,%2,%3},{%4,%5,%6,%7},{%8,%9},{%0,%1,%2,%3};"
        : "+f"(c[0]), "+f"(c[1]), "+f"(c[2]), "+f"(c[3])
        : "r"(a[0]), "r"(a[1]), "r"(a[2]), "r"(a[3]), "r"(b[0]), "r"(b[1]));
}

__device__ __forceinline__ void split2(float x, fp16& a0, fp16& a1) {
    a0 = __float2half_rn(x);
    a1 = __float2half_rn(x - __half2float(a0));
}
__device__ __forceinline__ float sigf(float x) { return 1.f / (1.f + expf(-x)); }

// ---- fused GEMM + LSTM cell, runtime npass/use_table, grid.z dispatch ----
// (BYTE-IDENTICAL to the verified 9.39ms version — do not touch)
__global__ __launch_bounds__(256, 2)
void gemm_cell_dyn(GArgs a0, GArgs a1)
{
    const GArgs& a = (blockIdx.z == 1) ? a1 : a0;
    extern __shared__ char smem[];
    const uint32_t sb = smem_u32(smem);
    const int tid  = threadIdx.x;
    const int wid  = tid >> 5;
    const int lane = tid & 31;
    const int row0 = blockIdx.y * CTA_M;
    const int col0 = blockIdx.x * CTA_N;
    const int warp_m = (wid & 3) * 32;
    const int warp_n = (wid >> 2) * 64;
    const int KSTEPS = a.npass * 16;

    if (!a.use_table && tid < CTA_N)
        ((float*)(smem + BIAS_OFF))[tid] = a.tb[col0 + tid];

    auto load_stage = [&](int s, int slot) {
        const int pass = s >> 4;
        const size_t k0b = (size_t)(s & 15) * 64;
        const char* srcs[4];
        srcs[0] = (const char*)(pass ? a.A20 : a.A10) + (size_t)row0 * (DD * 2) + k0b;
        srcs[1] = (const char*)(pass ? a.A21 : a.A11) + (size_t)row0 * (DD * 2) + k0b;
        srcs[2] = (const char*)(pass ? a.W20 : a.W10) + (size_t)col0 * (DD * 2) + k0b;
        srcs[3] = (const char*)(pass ? a.W21 : a.W11) + (size_t)col0 * (DD * 2) + k0b;
        const uint32_t base = sb + slot * STAGE_BYTES;
        #pragma unroll
        for (int tile = 0; tile < 4; tile++) {
            #pragma unroll
            for (int hh = 0; hh < 2; hh++) {
                int j = hh * 256 + tid;
                int r = j >> 2, u = j & 3;
                cpasync16(base + tile * 8192 + SWZ(r * 64 + u * 16),
                          srcs[tile] + (size_t)r * (DD * 2) + u * 16);
            }
        }
        CP_COMMIT();
    };

    float acc[2][8][4];
    #pragma unroll
    for (int i = 0; i < 2; i++)
        #pragma unroll
        for (int j = 0; j < 8; j++)
            #pragma unroll
            for (int k = 0; k < 4; k++) acc[i][j][k] = 0.f;

    const int laA = lane & 15;
    const int luA = lane >> 4;
    const int laB = (lane & 7) + ((lane >> 4) << 3);
    const int luB = (lane >> 3) & 1;

    if (KSTEPS > 0) {
        load_stage(0, 0);
        load_stage(1, 1);

        #pragma unroll 1
        for (int s = 0; s < KSTEPS; s++) {
            if (s + 2 < KSTEPS) load_stage(s + 2, (s + 2) % NSTAGE);
            else CP_COMMIT();
            CP_WAIT(2);
            __syncthreads();

            const uint32_t stg = sb + (s % NSTAGE) * STAGE_BYTES;
            #pragma unroll
            for (int kh = 0; kh < 2; kh++) {
                uint32_t A[2][2][4];
                #pragma unroll
                for (int am = 0; am < 2; am++) {
                    uint32_t off = SWZ((warp_m + am * 16 + laA) * 64 + kh * 32 + luA * 16);
                    ldsm4(A[0][am], stg + OFF_A0 + off);
                    ldsm4(A[1][am], stg + OFF_A1 + off);
                }
                #pragma unroll
                for (int g = 0; g < 4; g++) {
                    uint32_t Bf[2][4];
                    uint32_t offb = SWZ((warp_n + g * 16 + laB) * 64 + kh * 32 + luB * 16);
                    ldsm4(Bf[0], stg + OFF_B0 + offb);
                    ldsm4(Bf[1], stg + OFF_B1 + offb);
                    #pragma unroll
                    for (int am = 0; am < 2; am++)
                        #pragma unroll
                        for (int sub = 0; sub < 2; sub++) {
                            float* c = acc[am][g * 2 + sub];
                            mma16816(c, A[0][am], &Bf[0][sub * 2]);
                            mma16816(c, A[0][am], &Bf[1][sub * 2]);
                            mma16816(c, A[1][am], &Bf[0][sub * 2]);
                        }
                }
            }
            __syncthreads();
        }
    } else {
        __syncthreads();   // bias/table visibility for npass==0 path
    }

    // ---- fused LSTM cell epilogue ----
    const float* bias_s = (const float*)(smem + BIAS_OFF);
    const int q = lane & 3, r = lane >> 2;
    const int dbase = ((col0 + warp_n) >> 4) * 4 + q;
    #pragma unroll
    for (int am = 0; am < 2; am++) {
        #pragma unroll
        for (int half = 0; half < 2; half++) {
            const int m = row0 + warp_m + am * 16 + r + half * 8;
            const float* trow = nullptr;
            if (a.use_table) {
                int tv = a.tok[(size_t)m * a.tok_stride + a.tok_off];
                trow = a.tb + (size_t)tv * GG + col0 + warp_n + q * 2;
            }
            #pragma unroll
            for (int g16 = 0; g16 < 4; g16++) {
                float* aIF = acc[am][g16 * 2 + 0];
                float* aGO = acc[am][g16 * 2 + 1];
                float gi = aIF[half * 2 + 0], gf = aIF[half * 2 + 1];
                float gg = aGO[half * 2 + 0], go = aGO[half * 2 + 1];
                if (a.use_table) {
                    float2 t0 = *(const float2*)(trow + g16 * 16);
                    float2 t1 = *(const float2*)(trow + g16 * 16 + 8);
                    gi += t0.x; gf += t0.y; gg += t1.x; go += t1.y;
                } else {
                    int cb = warp_n + g16 * 16 + q * 2;
                    gi += bias_s[cb]; gf += bias_s[cb + 1];
                    gg += bias_s[cb + 8]; go += bias_s[cb + 9];
                }
                float I = sigf(gi), F = sigf(gf), G = tanhf(gg), O = sigf(go);
                int d = dbase + g16 * 4;
                size_t idx = (size_t)m * DD + d;
                float cn = F * a.cst[idx] + I * G;
                float hn = O * tanhf(cn);
                a.cst[idx] = cn;
                if (a.hf) a.hf[idx] = hn;
                fp16 v0, v1; split2(hn, v0, v1);
                a.h0o[idx] = v0; a.h1o[idx] = v1;
                if (a.x0o) { a.x0o[idx] = v0; a.x1o[idx] = v1; }
            }
        }
    }
}

// ---- decoder fused kernel: z < ncell -> table+cell; else -> raw-gate store ----
// Single-pass mainloop only (16 k-stages). Separate compilation unit from the
// encoder hot kernel; register budget independent.
__global__ __launch_bounds__(256, 2)
void dec_fused(DCArgs ac, DSArgs as, int ncell)
{
    const bool is_cell = ((int)blockIdx.z < ncell);
    extern __shared__ char smem[];
    const uint32_t sb = smem_u32(smem);
    const int tid  = threadIdx.x;
    const int wid  = tid >> 5;
    const int lane = tid & 31;
    const int row0 = blockIdx.y * CTA_M;
    const int col0 = blockIdx.x * CTA_N;
    const int warp_m = (wid & 3) * 32;
    const int warp_n = (wid >> 2) * 64;

    const fp16* A0 = is_cell ? ac.A0 : as.A0;
    const fp16* A1 = is_cell ? ac.A1 : as.A1;
    const fp16* W0 = is_cell ? ac.W0 : as.W0;
    const fp16* W1 = is_cell ? ac.W1 : as.W1;

    auto load_stage = [&](int s, int slot) {
        const size_t k0b = (size_t)s * 64;
        const char* srcs[4];
        srcs[0] = (const char*)A0 + (size_t)row0 * (DD * 2) + k0b;
        srcs[1] = (const char*)A1 + (size_t)row0 * (DD * 2) + k0b;
        srcs[2] = (const char*)W0 + (size_t)col0 * (DD * 2) + k0b;
        srcs[3] = (const char*)W1 + (size_t)col0 * (DD * 2) + k0b;
        const uint32_t base = sb + slot * STAGE_BYTES;
        #pragma unroll
        for (int tile = 0; tile < 4; tile++) {
            #pragma unroll
            for (int hh = 0; hh < 2; hh++) {
                int j = hh * 256 + tid;
                int r = j >> 2, u = j & 3;
                cpasync16(base + tile * 8192 + SWZ(r * 64 + u * 16),
                          srcs[tile] + (size_t)r * (DD * 2) + u * 16);
            }
        }
        CP_COMMIT();
    };

    float acc[2][8][4];
    #pragma unroll
    for (int i = 0; i < 2; i++)
        #pragma unroll
        for (int j = 0; j < 8; j++)
            #pragma unroll
            for (int k = 0; k < 4; k++) acc[i][j][k] = 0.f;

    const int laA = lane & 15;
    const int luA = lane >> 4;
    const int laB = (lane & 7) + ((lane >> 4) << 3);
    const int luB = (lane >> 3) & 1;

    load_stage(0, 0);
    load_stage(1, 1);

    #pragma unroll 1
    for (int s = 0; s < 16; s++) {
        if (s + 2 < 16) load_stage(s + 2, (s + 2) % NSTAGE);
        else CP_COMMIT();
        CP_WAIT(2);
        __syncthreads();

        const uint32_t stg = sb + (s % NSTAGE) * STAGE_BYTES;
        #pragma unroll
        for (int kh = 0; kh < 2; kh++) {
            uint32_t A[2][2][4];
            #pragma unroll
            for (int am = 0; am < 2; am++) {
                uint32_t off = SWZ((warp_m + am * 16 + laA) * 64 + kh * 32 + luA * 16);
                ldsm4(A[0][am], stg + OFF_A0 + off);
                ldsm4(A[1][am], stg + OFF_A1 + off);
            }
            #pragma unroll
            for (int g = 0; g < 4; g++) {
                uint32_t Bf[2][4];
                uint32_t offb = SWZ((warp_n + g * 16 + laB) * 64 + kh * 32 + luB * 16);
                ldsm4(Bf[0], stg + OFF_B0 + offb);
                ldsm4(Bf[1], stg + OFF_B1 + offb);
                #pragma unroll
                for (int am = 0; am < 2; am++)
                    #pragma unroll
                    for (int sub = 0; sub < 2; sub++) {
                        float* c = acc[am][g * 2 + sub];
                        mma16816(c, A[0][am], &Bf[0][sub * 2]);
                        mma16816(c, A[0][am], &Bf[1][sub * 2]);
                        mma16816(c, A[1][am], &Bf[0][sub * 2]);
                    }
            }
        }
        __syncthreads();
    }

    const int q = lane & 3, r = lane >> 2;
    if (is_cell) {
        const int dbase = ((col0 + warp_n) >> 4) * 4 + q;
        #pragma unroll
        for (int am = 0; am < 2; am++) {
            #pragma unroll
            for (int half = 0; half < 2; half++) {
                const int m = row0 + warp_m + am * 16 + r + half * 8;
                int tv = ac.tok[(size_t)m * ac.tok_stride + ac.tok_off];
                const float* trow = ac.tb + (size_t)tv * GG + col0 + warp_n + q * 2;
                #pragma unroll
                for (int g16 = 0; g16 < 4; g16++) {
                    float* aIF = acc[am][g16 * 2 + 0];
                    float* aGO = acc[am][g16 * 2 + 1];
                    float2 t0 = *(const float2*)(trow + g16 * 16);
                    float2 t1 = *(const float2*)(trow + g16 * 16 + 8);
                    float gi = aIF[half * 2 + 0] + t0.x;
                    float gf = aIF[half * 2 + 1] + t0.y;
                    float gg = aGO[half * 2 + 0] + t1.x;
                    float go = aGO[half * 2 + 1] + t1.y;
                    float I = sigf(gi), F = sigf(gf), G = tanhf(gg), O = sigf(go);
                    int d = dbase + g16 * 4;
                    size_t idx = (size_t)m * DD + d;
                    float cn = F * ac.cst[idx] + I * G;
                    float hn = O * tanhf(cn);
                    ac.cst[idx] = cn;
                    fp16 v0, v1; split2(hn, v0, v1);
                    ac.h0o[idx] = v0; ac.h1o[idx] = v1;
                }
            }
        }
    } else {
        #pragma unroll
        for (int am = 0; am < 2; am++) {
            #pragma unroll
            for (int half = 0; half < 2; half++) {
                const int m = row0 + warp_m + am * 16 + r + half * 8;
                #pragma unroll
                for (int g16 = 0; g16 < 4; g16++) {
                    float* aIF = acc[am][g16 * 2 + 0];
                    float* aGO = acc[am][g16 * 2 + 1];
                    const int cb = warp_n + g16 * 16 + q * 2;
                    const size_t gidx = (size_t)m * GG + col0 + cb;
                    *(float2*)&as.gates[gidx]     = make_float2(aIF[half * 2 + 0], aIF[half * 2 + 1]);
                    *(float2*)&as.gates[gidx + 8] = make_float2(aGO[half * 2 + 0], aGO[half * 2 + 1]);
                }
            }
        }
    }
}

// ---- single-pass GEMM + stored gates + bias -> LSTM cell (decoder l1 x-pass) ----
__global__ __launch_bounds__(256, 2)
void gemm_addcell_k(const fp16* __restrict__ A0p, const fp16* __restrict__ A1p,
                    const fp16* __restrict__ W0p, const fp16* __restrict__ W1p,
                    const float* __restrict__ bias, const float* __restrict__ gates,
                    float* __restrict__ cst, float* __restrict__ hf,
                    fp16* __restrict__ h0o, fp16* __restrict__ h1o)
{
    extern __shared__ char smem[];
    const uint32_t sb = smem_u32(smem);
    const int tid  = threadIdx.x;
    const int wid  = tid >> 5;
    const int lane = tid & 31;
    const int row0 = blockIdx.y * CTA_M;
    const int col0 = blockIdx.x * CTA_N;
    const int warp_m = (wid & 3) * 32;
    const int warp_n = (wid >> 2) * 64;

    if (tid < CTA_N)
        ((float*)(smem + BIAS_OFF))[tid] = bias[col0 + tid];

    auto load_stage = [&](int s, int slot) {
        const size_t k0b = (size_t)s * 64;
        const char* srcs[4];
        srcs[0] = (const char*)A0p + (size_t)row0 * (DD * 2) + k0b;
        srcs[1] = (const char*)A1p + (size_t)row0 * (DD * 2) + k0b;
        srcs[2] = (const char*)W0p + (size_t)col0 * (DD * 2) + k0b;
        srcs[3] = (const char*)W1p + (size_t)col0 * (DD * 2) + k0b;
        const uint32_t base = sb + slot * STAGE_BYTES;
        #pragma unroll
        for (int tile = 0; tile < 4; tile++) {
            #pragma unroll
            for (int hh = 0; hh < 2; hh++) {
                int j = hh * 256 + tid;
                int r = j >> 2, u = j & 3;
                cpasync16(base + tile * 8192 + SWZ(r * 64 + u * 16),
                          srcs[tile] + (size_t)r * (DD * 2) + u * 16);
            }
        }
        CP_COMMIT();
    };

    float acc[2][8][4];
    #pragma unroll
    for (int i = 0; i < 2; i++)
        #pragma unroll
        for (int j = 0; j < 8; j++)
            #pragma unroll
            for (int k = 0; k < 4; k++) acc[i][j][k] = 0.f;

    const int laA = lane & 15;
    const int luA = lane >> 4;
    const int laB = (lane & 7) + ((lane >> 4) << 3);
    const int luB = (lane >> 3) & 1;

    load_stage(0, 0);
    load_stage(1, 1);

    #pragma unroll 1
    for (int s = 0; s < 16; s++) {
        if (s + 2 < 16) load_stage(s + 2, (s + 2) % NSTAGE);
        else CP_COMMIT();
        CP_WAIT(2);
        __syncthreads();

        const uint32_t stg = sb + (s % NSTAGE) * STAGE_BYTES;
        #pragma unroll
        for (int kh = 0; kh < 2; kh++) {
            uint32_t A[2][2][4];
            #pragma unroll
            for (int am = 0; am < 2; am++) {
                uint32_t off = SWZ((warp_m + am * 16 + laA) * 64 + kh * 32 + luA * 16);
                ldsm4(A[0][am], stg + OFF_A0 + off);
                ldsm4(A[1][am], stg + OFF_A1 + off);
            }
            #pragma unroll
            for (int g = 0; g < 4; g++) {
                uint32_t Bf[2][4];
                uint32_t offb = SWZ((warp_n + g * 16 + laB) * 64 + kh * 32 + luB * 16);
                ldsm4(Bf[0], stg + OFF_B0 + offb);
                ldsm4(Bf[1], stg + OFF_B1 + offb);
                #pragma unroll
                for (int am = 0; am < 2; am++)
                    #pragma unroll
                    for (int sub = 0; sub < 2; sub++) {
                        float* c = acc[am][g * 2 + sub];
                        mma16816(c, A[0][am], &Bf[0][sub * 2]);
                        mma16816(c, A[0][am], &Bf[1][sub * 2]);
                        mma16816(c, A[1][am], &Bf[0][sub * 2]);
                    }
            }
        }
        __syncthreads();
    }

    // epilogue: + bias + stored gates -> cell
    const float* bias_s = (const float*)(smem + BIAS_OFF);
    const int q = lane & 3, r = lane >> 2;
    const int dbase = ((col0 + warp_n) >> 4) * 4 + q;
    #pragma unroll
    for (int am = 0; am < 2; am++) {
        #pragma unroll
        for (int half = 0; half < 2; half++) {
            const int m = row0 + warp_m + am * 16 + r + half * 8;
            #pragma unroll
            for (int g16 = 0; g16 < 4; g16++) {
                float* aIF = acc[am][g16 * 2 + 0];
                float* aGO = acc[am][g16 * 2 + 1];
                const int cb = warp_n + g16 * 16 + q * 2;
                const size_t gidx = (size_t)m * GG + col0 + cb;
                float2 p0v = *(const float2*)&gates[gidx];
                float2 p1v = *(const float2*)&gates[gidx + 8];
                float gi = aIF[half * 2 + 0] + bias_s[cb]     + p0v.x;
                float gf = aIF[half * 2 + 1] + bias_s[cb + 1] + p0v.y;
                float gg = aGO[half * 2 + 0] + bias_s[cb + 8] + p1v.x;
                float go = aGO[half * 2 + 1] + bias_s[cb + 9] + p1v.y;
                float I = sigf(gi), F = sigf(gf), G = tanhf(gg), O = sigf(go);
                int d = dbase + g16 * 4;
                size_t idx = (size_t)m * DD + d;
                float cn = F * cst[idx] + I * G;
                float hn = O * tanhf(cn);
                cst[idx] = cn;
                hf[idx] = hn;
                fp16 v0, v1; split2(hn, v0, v1);
                h0o[idx] = v0; h1o[idx] = v1;
            }
        }
    }
}

// ---------------- encoder t=0 init ----------------
__global__ void enc0_init(const int* __restrict__ src, const float* __restrict__ encT,
                          float* __restrict__ cst0,
                          fp16* __restrict__ h0o, fp16* __restrict__ h1o,
                          fp16* __restrict__ x0o, fp16* __restrict__ x1o)
{
    int idx = blockIdx.x * 256 + threadIdx.x;
    if (idx >= BB * DD) return;
    int b = idx >> 9, d = idx & 511;
    int tok = src[b * TSRC + 0];
    const float* row = encT + (size_t)tok * GG;
    int cbase = ((d >> 2) << 4) + ((d & 3) << 1);
    float gi = row[cbase + 0];
    float gf = row[cbase + 1];
    float gg = row[cbase + 8];
    float go = row[cbase + 9];
    float I = sigf(gi), F = sigf(gf), G = tanhf(gg), O = sigf(go);
    float cn = F * 0.f + I * G;
    float hn = O * tanhf(cn);
    cst0[idx] = cn;
    fp16 v0, v1; split2(hn, v0, v1);
    h0o[idx] = v0; h1o[idx] = v1;
    x0o[idx] = v0; x1o[idx] = v1;
}

// ---------------- fused prep kernels ----------------
__global__ void permsplit_all(const float* w0, const float* w1, const float* w2,
                              const float* w3, const float* w4, const float* w5,
                              fp16* __restrict__ P0, fp16* __restrict__ P1)
{
    const float* srcs[6] = { w0, w1, w2, w3, w4, w5 };
    int mtx = blockIdx.y;
    size_t base = (size_t)mtx * GG * DD;
    size_t i = (size_t)blockIdx.x * 256 + threadIdx.x;
    if (i >= (size_t)GG * DD) return;
    int n = (int)(i >> 9), k = (int)(i & 511);
    int g = n >> 9, d = n & 511;
    int c = ((d >> 2) << 4) + ((d & 3) << 1) + ((g >> 1) << 3) + (g & 1);
    fp16 a0, a1;
    split2(srcs[mtx][i], a0, a1);
    size_t o = base + ((size_t)c << 9) + k;
    P0[o] = a0; P1[o] = a1;
}

__global__ void permbias_all(const float* e1, const float* e2,
                             const float* d1, const float* d2,
                             float* __restrict__ bE, float* __restrict__ bD)
{
    int n = blockIdx.x * 256 + threadIdx.x;
    if (n >= GG) return;
    int g = n >> 9, d = n & 511;
    int c = ((d >> 2) << 4) + ((d & 3) << 1) + ((g >> 1) << 3) + (g & 1);
    bE[c] = e1[n] + e2[n];
    bD[c] = d1[n] + d2[n];
}

__global__ void table_all(const float* __restrict__ eemb, const float* __restrict__ eW,
                          const float* __restrict__ eb1, const float* __restrict__ eb2,
                          const float* __restrict__ demb, const float* __restrict__ dW,
                          const float* __restrict__ db1, const float* __restrict__ db2,
                          float* __restrict__ eT, float* __restrict__ dT)
{
    __shared__ float es[DD];
    int v = blockIdx.x;
    bool enc = v < DSRC;
    int vv = enc ? v : v - DSRC;
    const float* emb = enc ? eemb : demb;
    const float* W   = enc ? eW : dW;
    const float* b1  = enc ? eb1 : db1;
    const float* b2  = enc ? eb2 : db2;
    float* T         = enc ? eT : dT;
    int c = blockIdx.y * 128 + threadIdx.x;
    for (int i = threadIdx.x; i < DD; i += 128) es[i] = emb[(size_t)vv * DD + i];
    __syncthreads();
    int d = ((c >> 4) << 2) + ((c >> 1) & 3);
    int g = (((c >> 3) & 1) << 1) + (c & 1);
    int n = g * 512 + d;
    const float* w = W + (size_t)n * DD;
    float acc = b1[n] + b2[n];
    #pragma unroll 8
    for (int k = 0; k < DD; k++) acc = fmaf(es[k], w[k], acc);
    T[(size_t)vv * GG + c] = acc;
}

// ---------------- warp-reduced logits + argmax (R11 version) ----------------
__global__ void logits_argmax_kernel(const float* __restrict__ h,
                                     const float* __restrict__ W,
                                     const float* __restrict__ bias,
                                     float* __restrict__ out, int t,
                                     int* __restrict__ pred)
{
    __shared__ float hs[DD];
    __shared__ float lg[DTGT];
    int b = blockIdx.x;
    int tid = threadIdx.x, wid = tid >> 5, lane = tid & 31;
    for (int i = tid; i < DD; i += 256)
        hs[i] = h[(size_t)b * DD + i];
    __syncthreads();
    #pragma unroll
    for (int j = 0; j < 10; j++) {
        int n = wid * 10 + j;
        const float* w = W + (size_t)n * DD;
        float acc = 0.f;
        #pragma unroll
        for (int k = lane; k < DD; k += 32) acc = fmaf(hs[k], w[k], acc);
        #pragma unroll
        for (int o = 16; o; o >>= 1) acc += __shfl_xor_sync(0xFFFFFFFFu, acc, o);
        if (lane == 0) {
            float v = acc + bias[n];
            lg[n] = v;
            out[(size_t)b * (TTGT * DTGT) + t * DTGT + n] = v;
        }
    }
    __syncthreads();
    if (tid == 0) {
        float best = lg[0];
        int bi = 0;
        for (int i = 1; i < DTGT; i++)
            if (lg[i] > best) { best = lg[i]; bi = i; }
        pred[b] = bi;
    }
}

// ---------------- host orchestration ----------------
extern "C" void kernel_launch(void* const* d_in, const int* in_sizes, int n_in,
                              void* d_out, int out_size)
{
    const int*   src     = (const int*)  d_in[0];
    const int*   tgt     = (const int*)  d_in[1];
    const float* enc_emb = (const float*)d_in[2];
    const float* dec_emb = (const float*)d_in[3];
    const float* enc_Wih = (const float*)d_in[4];
    const float* enc_Whh = (const float*)d_in[5];
    const float* enc_bih = (const float*)d_in[6];
    const float* enc_bhh = (const float*)d_in[7];
    const float* dec_Wih = (const float*)d_in[8];
    const float* dec_Whh = (const float*)d_in[9];
    const float* dec_bih = (const float*)d_in[10];
    const float* dec_bhh = (const float*)d_in[11];
    const float* post_W  = (const float*)d_in[12];
    const float* post_b  = (const float*)d_in[13];
    float* out = (float*)d_out;

    cudaFuncSetAttribute(gemm_cell_dyn,  cudaFuncAttributeMaxDynamicSharedMemorySize, SMEM_TOTAL_GEMM);
    cudaFuncSetAttribute(dec_fused,      cudaFuncAttributeMaxDynamicSharedMemorySize, SMEM_STORE);
    cudaFuncSetAttribute(gemm_addcell_k, cudaFuncAttributeMaxDynamicSharedMemorySize, SMEM_TOTAL_GEMM);

    fp16 *Xs0, *Xs1, *Wp0, *Wp1, *hp0, *hp1;
    float *cst, *hf, *gH, *encT, *decT, *biasE, *biasD;
    int* pred;
    cudaGetSymbolAddress((void**)&Xs0, g_Xs0);
    cudaGetSymbolAddress((void**)&Xs1, g_Xs1);
    cudaGetSymbolAddress((void**)&Wp0, g_Wp0);
    cudaGetSymbolAddress((void**)&Wp1, g_Wp1);
    cudaGetSymbolAddress((void**)&hp0, g_hp0);
    cudaGetSymbolAddress((void**)&hp1, g_hp1);
    cudaGetSymbolAddress((void**)&cst, g_c);
    cudaGetSymbolAddress((void**)&hf,  g_hf);
    cudaGetSymbolAddress((void**)&gH,  g_gatesH);
    cudaGetSymbolAddress((void**)&encT, g_encT);
    cudaGetSymbolAddress((void**)&decT, g_decT);
    cudaGetSymbolAddress((void**)&biasE, g_biasE);
    cudaGetSymbolAddress((void**)&biasD, g_biasD);
    cudaGetSymbolAddress((void**)&pred, g_pred);

    const size_t WSL = (size_t)GG * DD;
    const size_t HB  = (size_t)BB * DD;

    cudaMemsetAsync(cst + HB, 0, HB * sizeof(float), 0);

    // prep (3 kernels)
    permsplit_all<<<dim3((unsigned)((WSL + 255) / 256), 6), 256>>>(
        enc_Whh, enc_Wih + WSL, enc_Whh + WSL, dec_Whh, dec_Wih + WSL, dec_Whh + WSL, Wp0, Wp1);
    permbias_all<<<(GG + 255) / 256, 256>>>(enc_bih + GG, enc_bhh + GG,
                                            dec_bih + GG, dec_bhh + GG, biasE, biasD);
    table_all<<<dim3(DSRC + DTGT, GG / 128), 128>>>(
        enc_emb, enc_Wih, enc_bih, enc_bhh, dec_emb, dec_Wih, dec_bih, dec_bhh, encT, decT);

    int p0 = 0, p1 = 0;

    // ---- encoder t=0 via elementwise init ----
    enc0_init<<<(BB * DD + 255) / 256, 256>>>(src, encT, cst,
        hp0 + (0 * 2 + 1) * HB, hp1 + (0 * 2 + 1) * HB, Xs0, Xs1);
    p0 = 1;

    auto mk_l0_enc = [&](int t) {
        GArgs a = {};
        a.A10 = hp0 + (0 * 2 + p0) * HB;  a.A11 = hp1 + (0 * 2 + p0) * HB;
        a.W10 = Wp0 + 0 * WSL;            a.W11 = Wp1 + 0 * WSL;
        a.tb = encT; a.tok = src; a.tok_stride = TSRC; a.tok_off = t;
        a.cst = cst + 0 * HB; a.hf = nullptr;
        a.h0o = hp0 + (0 * 2 + (p0 ^ 1)) * HB;  a.h1o = hp1 + (0 * 2 + (p0 ^ 1)) * HB;
        a.x0o = Xs0 + (size_t)t * HB;  a.x1o = Xs1 + (size_t)t * HB;
        a.npass = 1; a.use_table = 1;
        return a;
    };
    auto mk_l1_enc = [&](int t) {
        GArgs a = {};
        a.A10 = Xs0 + (size_t)t * HB;  a.A11 = Xs1 + (size_t)t * HB;
        a.W10 = Wp0 + 1 * WSL;         a.W11 = Wp1 + 1 * WSL;
        a.A20 = hp0 + (1 * 2 + p1) * HB;  a.A21 = hp1 + (1 * 2 + p1) * HB;
        a.W20 = Wp0 + 2 * WSL;            a.W21 = Wp1 + 2 * WSL;
        a.tb = biasE; a.tok = nullptr; a.tok_stride = 0; a.tok_off = 0;
        a.cst = cst + 1 * HB; a.hf = nullptr;
        a.h0o = hp0 + (1 * 2 + (p1 ^ 1)) * HB;  a.h1o = hp1 + (1 * 2 + (p1 ^ 1)) * HB;
        a.x0o = nullptr; a.x1o = nullptr;
        a.npass = (t == 0) ? 1 : 2; a.use_table = 0;
        return a;
    };
    auto mk_l0_dec0 = [&]() {   // decoder l0 at t=0 (tokens = tgt[:,0])
        GArgs a = {};
        a.A10 = hp0 + (0 * 2 + p0) * HB;  a.A11 = hp1 + (0 * 2 + p0) * HB;
        a.W10 = Wp0 + 3 * WSL;            a.W11 = Wp1 + 3 * WSL;
        a.tb = decT; a.tok = tgt; a.tok_stride = TTGT; a.tok_off = 0;
        a.cst = cst + 0 * HB; a.hf = nullptr;
        a.h0o = hp0 + (0 * 2 + (p0 ^ 1)) * HB;  a.h1o = hp1 + (0 * 2 + (p0 ^ 1)) * HB;
        a.x0o = nullptr; a.x1o = nullptr;
        a.npass = 1; a.use_table = 1;
        return a;
    };

    // ---- encoder: diagonal waves tau = 1..TSRC ----
    for (int tau = 1; tau <= TSRC; tau++) {
        if (tau < TSRC) {
            GArgs a0 = mk_l0_enc(tau);
            GArgs a1 = mk_l1_enc(tau - 1);
            gemm_cell_dyn<<<dim3(GG / CTA_N, NROWB, 2), 256, SMEM_TOTAL_GEMM>>>(a0, a1);
            p0 ^= 1; p1 ^= 1;
        } else {
            // final wave: enc l1[31]  +  dec l0[0]  (independent, z=2)
            GArgs a0 = mk_l1_enc(tau - 1);
            GArgs a1 = mk_l0_dec0();
            gemm_cell_dyn<<<dim3(GG / CTA_N, NROWB, 2), 256, SMEM_TOTAL_GEMM>>>(a0, a1);
            p1 ^= 1; p0 ^= 1;
        }
    }

    // ---- decoder: hstore[0] -> { addcell[t] -> logits[t] -> (l0[t+1] || hstore[t+1]) } ----
    auto mk_store = [&]() {
        DSArgs s = {};
        s.A0 = hp0 + (1 * 2 + p1) * HB;  s.A1 = hp1 + (1 * 2 + p1) * HB;
        s.W0 = Wp0 + 5 * WSL;            s.W1 = Wp1 + 5 * WSL;
        s.gates = gH;
        return s;
    };
    {
        DCArgs dummy = {};
        DSArgs s0 = mk_store();
        dec_fused<<<dim3(GG / CTA_N, NROWB, 1), 256, SMEM_STORE>>>(dummy, s0, 0);
    }

    for (int t = 0; t < TTGT; t++) {
        // x-pass + stored h-gates + bias -> cell -> h1, hf
        gemm_addcell_k<<<dim3(GG / CTA_N, NROWB, 1), 256, SMEM_TOTAL_GEMM>>>(
            hp0 + (0 * 2 + p0) * HB, hp1 + (0 * 2 + p0) * HB,   // l0[t] output
            Wp0 + 4 * WSL, Wp1 + 4 * WSL,
            biasD, gH,
            cst + HB, hf,
            hp0 + (1 * 2 + (p1 ^ 1)) * HB, hp1 + (1 * 2 + (p1 ^ 1)) * HB);
        p1 ^= 1;

        logits_argmax_kernel<<<BB, 256>>>(hf, post_W, post_b, out, t, pred);

        if (t + 1 < TTGT) {
            // fused wave: z=0 l0[t+1] (table+cell), z=1 hstore[t+1]
            DCArgs c = {};
            c.A0 = hp0 + (0 * 2 + p0) * HB;  c.A1 = hp1 + (0 * 2 + p0) * HB;
            c.W0 = Wp0 + 3 * WSL;            c.W1 = Wp1 + 3 * WSL;
            c.tb = decT; c.tok = pred; c.tok_stride = 1; c.tok_off = 0;
            c.cst = cst + 0 * HB;
            c.h0o = hp0 + (0 * 2 + (p0 ^ 1)) * HB;  c.h1o = hp1 + (0 * 2 + (p0 ^ 1)) * HB;
            DSArgs s = mk_store();
            dec_fused<<<dim3(GG / CTA_N, NROWB, 2), 256, SMEM_STORE>>>(c, s, 1);
            p0 ^= 1;
        }
    }
}

// round 16
// speedup vs baseline: 1.0460x; 1.0152x over previous
#include <cuda_runtime.h>
#include <cuda_fp16.h>
#include <math.h>
#include <stdint.h>

// Problem constants
#define BB    2048
#define DD    512
#define GG    2048
#define TSRC  32
#define TTGT  32
#define DTGT  80
#define DSRC  100
#define NL    2

// GEMM tiling
#define CTA_M 128
#define CTA_N 128
#define NSTAGE 3
#define NROWB (BB / CTA_M)    // 16

#define STAGE_BYTES 32768
#define OFF_A0 0
#define OFF_A1 8192
#define OFF_B0 16384
#define OFF_B1 24576
#define BIAS_OFF (NSTAGE * STAGE_BYTES)          // 98304
#define SMEM_TOTAL_GEMM (BIAS_OFF + CTA_N * 4)   // 98816

#define SWZ(x) ((uint32_t)(x) ^ ((((uint32_t)(x)) >> 3) & 0x70))

typedef __half fp16;

// ---------------- persistent scratch ----------------
// permuted+split weights: [0]=encWhh0 [1]=encWih1 [2]=encWhh1 [3]=decWhh0 [4]=decWih1 [5]=decWhh1
__device__ __align__(256) fp16 g_Wp0[6][(size_t)GG * DD];
__device__ __align__(256) fp16 g_Wp1[6][(size_t)GG * DD];
__device__ __align__(256) fp16 g_hp0[NL][2][(size_t)BB * DD];
__device__ __align__(256) fp16 g_hp1[NL][2][(size_t)BB * DD];
__device__ float g_c[NL][(size_t)BB * DD];
__device__ float g_hf[(size_t)BB * DD];
__device__ float g_encT[(size_t)DSRC * GG];
__device__ float g_decT[(size_t)DTGT * GG];
__device__ float g_biasE[GG];
__device__ float g_biasD[GG];
__device__ int   g_pred[BB];

// ---------------- arg struct for runtime-dispatch GEMM ----------------
struct GArgs {
    const fp16 *A10, *A11, *W10, *W11;   // pass-0 operands
    const fp16 *A20, *A21, *W20, *W21;   // pass-1 operands
    const float* tb;                      // table (use_table) or permuted bias
    const int* tok; int tok_stride, tok_off;
    float* cst; float* hf;
    fp16 *h0o, *h1o, *x0o, *x1o;
    int npass; int use_table;
};

// ---------------- PTX helpers ----------------
__device__ __forceinline__ uint32_t smem_u32(const void* p) {
    uint32_t a;
    asm("{ .reg .u64 t; cvta.to.shared.u64 t, %1; cvt.u32.u64 %0, t; }" : "=r"(a) : "l"(p));
    return a;
}
__device__ __forceinline__ void cpasync16(uint32_t dst, const void* src) {
    asm volatile("cp.async.cg.shared.global [%0], [%1], 16;" :: "r"(dst), "l"(src));
}
#define CP_COMMIT()  asm volatile("cp.async.commit_group;" ::: "memory")
#define CP_WAIT(n)   asm volatile("cp.async.wait_group %0;" :: "n"(n) : "memory")

__device__ __forceinline__ void ldsm4(uint32_t* d, uint32_t addr) {
    asm volatile("ldmatrix.sync.aligned.m8n8.x4.shared.b16 {%0,%1,%2,%3}, [%4];"
        : "=r"(d[0]), "=r"(d[1]), "=r"(d[2]), "=r"(d[3]) : "r"(addr));
}
__device__ __forceinline__ void mma16816(float* c, const uint32_t* a, const uint32_t* b) {
    asm volatile(
        "mma.sync.aligned.m16n8k16.row.col.f32.f16.f16.f32 "
        "{%0,%1,%2,%3},{%4,%5,%6,%7},{%8,%9},{%0,%1,%2,%3};"
        : "+f"(c[0]), "+f"(c[1]), "+f"(c[2]), "+f"(c[3])
        : "r"(a[0]), "r"(a[1]), "r"(a[2]), "r"(a[3]), "r"(b[0]), "r"(b[1]));
}

__device__ __forceinline__ void split2(float x, fp16& a0, fp16& a1) {
    a0 = __float2half_rn(x);
    a1 = __float2half_rn(x - __half2float(a0));
}
__device__ __forceinline__ float sigf(float x) { return 1.f / (1.f + expf(-x)); }

// ---- fused GEMM + LSTM cell, runtime npass/use_table, grid.z dispatch ----
// (BYTE-IDENTICAL to the verified 9.39ms version — do not touch)
__global__ __launch_bounds__(256, 2)
void gemm_cell_dyn(GArgs a0, GArgs a1)
{
    const GArgs& a = (blockIdx.z == 1) ? a1 : a0;
    extern __shared__ char smem[];
    const uint32_t sb = smem_u32(smem);
    const int tid  = threadIdx.x;
    const int wid  = tid >> 5;
    const int lane = tid & 31;
    const int row0 = blockIdx.y * CTA_M;
    const int col0 = blockIdx.x * CTA_N;
    const int warp_m = (wid & 3) * 32;
    const int warp_n = (wid >> 2) * 64;
    const int KSTEPS = a.npass * 16;

    if (!a.use_table && tid < CTA_N)
        ((float*)(smem + BIAS_OFF))[tid] = a.tb[col0 + tid];

    auto load_stage = [&](int s, int slot) {
        const int pass = s >> 4;
        const size_t k0b = (size_t)(s & 15) * 64;
        const char* srcs[4];
        srcs[0] = (const char*)(pass ? a.A20 : a.A10) + (size_t)row0 * (DD * 2) + k0b;
        srcs[1] = (const char*)(pass ? a.A21 : a.A11) + (size_t)row0 * (DD * 2) + k0b;
        srcs[2] = (const char*)(pass ? a.W20 : a.W10) + (size_t)col0 * (DD * 2) + k0b;
        srcs[3] = (const char*)(pass ? a.W21 : a.W11) + (size_t)col0 * (DD * 2) + k0b;
        const uint32_t base = sb + slot * STAGE_BYTES;
        #pragma unroll
        for (int tile = 0; tile < 4; tile++) {
            #pragma unroll
            for (int hh = 0; hh < 2; hh++) {
                int j = hh * 256 + tid;
                int r = j >> 2, u = j & 3;
                cpasync16(base + tile * 8192 + SWZ(r * 64 + u * 16),
                          srcs[tile] + (size_t)r * (DD * 2) + u * 16);
            }
        }
        CP_COMMIT();
    };

    float acc[2][8][4];
    #pragma unroll
    for (int i = 0; i < 2; i++)
        #pragma unroll
        for (int j = 0; j < 8; j++)
            #pragma unroll
            for (int k = 0; k < 4; k++) acc[i][j][k] = 0.f;

    const int laA = lane & 15;
    const int luA = lane >> 4;
    const int laB = (lane & 7) + ((lane >> 4) << 3);
    const int luB = (lane >> 3) & 1;

    if (KSTEPS > 0) {
        load_stage(0, 0);
        load_stage(1, 1);

        #pragma unroll 1
        for (int s = 0; s < KSTEPS; s++) {
            if (s + 2 < KSTEPS) load_stage(s + 2, (s + 2) % NSTAGE);
            else CP_COMMIT();
            CP_WAIT(2);
            __syncthreads();

            const uint32_t stg = sb + (s % NSTAGE) * STAGE_BYTES;
            #pragma unroll
            for (int kh = 0; kh < 2; kh++) {
                uint32_t A[2][2][4];
                #pragma unroll
                for (int am = 0; am < 2; am++) {
                    uint32_t off = SWZ((warp_m + am * 16 + laA) * 64 + kh * 32 + luA * 16);
                    ldsm4(A[0][am], stg + OFF_A0 + off);
                    ldsm4(A[1][am], stg + OFF_A1 + off);
                }
                #pragma unroll
                for (int g = 0; g < 4; g++) {
                    uint32_t Bf[2][4];
                    uint32_t offb = SWZ((warp_n + g * 16 + laB) * 64 + kh * 32 + luB * 16);
                    ldsm4(Bf[0], stg + OFF_B0 + offb);
                    ldsm4(Bf[1], stg + OFF_B1 + offb);
                    #pragma unroll
                    for (int am = 0; am < 2; am++)
                        #pragma unroll
                        for (int sub = 0; sub < 2; sub++) {
                            float* c = acc[am][g * 2 + sub];
                            mma16816(c, A[0][am], &Bf[0][sub * 2]);
                            mma16816(c, A[0][am], &Bf[1][sub * 2]);
                            mma16816(c, A[1][am], &Bf[0][sub * 2]);
                        }
                }
            }
            __syncthreads();
        }
    } else {
        __syncthreads();   // bias/table visibility for npass==0 path
    }

    // ---- fused LSTM cell epilogue ----
    const float* bias_s = (const float*)(smem + BIAS_OFF);
    const int q = lane & 3, r = lane >> 2;
    const int dbase = ((col0 + warp_n) >> 4) * 4 + q;
    #pragma unroll
    for (int am = 0; am < 2; am++) {
        #pragma unroll
        for (int half = 0; half < 2; half++) {
            const int m = row0 + warp_m + am * 16 + r + half * 8;
            const float* trow = nullptr;
            if (a.use_table) {
                int tv = a.tok[(size_t)m * a.tok_stride + a.tok_off];
                trow = a.tb + (size_t)tv * GG + col0 + warp_n + q * 2;
            }
            #pragma unroll
            for (int g16 = 0; g16 < 4; g16++) {
                float* aIF = acc[am][g16 * 2 + 0];
                float* aGO = acc[am][g16 * 2 + 1];
                float gi = aIF[half * 2 + 0], gf = aIF[half * 2 + 1];
                float gg = aGO[half * 2 + 0], go = aGO[half * 2 + 1];
                if (a.use_table) {
                    float2 t0 = *(const float2*)(trow + g16 * 16);
                    float2 t1 = *(const float2*)(trow + g16 * 16 + 8);
                    gi += t0.x; gf += t0.y; gg += t1.x; go += t1.y;
                } else {
                    int cb = warp_n + g16 * 16 + q * 2;
                    gi += bias_s[cb]; gf += bias_s[cb + 1];
                    gg += bias_s[cb + 8]; go += bias_s[cb + 9];
                }
                float I = sigf(gi), F = sigf(gf), G = tanhf(gg), O = sigf(go);
                int d = dbase + g16 * 4;
                size_t idx = (size_t)m * DD + d;
                float cn = F * a.cst[idx] + I * G;
                float hn = O * tanhf(cn);
                a.cst[idx] = cn;
                if (a.hf) a.hf[idx] = hn;
                fp16 v0, v1; split2(hn, v0, v1);
                a.h0o[idx] = v0; a.h1o[idx] = v1;
                if (a.x0o) { a.x0o[idx] = v0; a.x1o[idx] = v1; }
            }
        }
    }
}

// ---------------- encoder t=0 init (no Xs writes anymore) ----------------
__global__ void enc0_init(const int* __restrict__ src, const float* __restrict__ encT,
                          float* __restrict__ cst0,
                          fp16* __restrict__ h0o, fp16* __restrict__ h1o)
{
    int idx = blockIdx.x * 256 + threadIdx.x;
    if (idx >= BB * DD) return;
    int b = idx >> 9, d = idx & 511;
    int tok = src[b * TSRC + 0];
    const float* row = encT + (size_t)tok * GG;
    int cbase = ((d >> 2) << 4) + ((d & 3) << 1);
    float gi = row[cbase + 0];
    float gf = row[cbase + 1];
    float gg = row[cbase + 8];
    float go = row[cbase + 9];
    float I = sigf(gi), F = sigf(gf), G = tanhf(gg), O = sigf(go);
    float cn = F * 0.f + I * G;
    float hn = O * tanhf(cn);
    cst0[idx] = cn;
    fp16 v0, v1; split2(hn, v0, v1);
    h0o[idx] = v0; h1o[idx] = v1;
}

// ---------------- fused prep kernels ----------------
__global__ void permsplit_all(const float* w0, const float* w1, const float* w2,
                              const float* w3, const float* w4, const float* w5,
                              fp16* __restrict__ P0, fp16* __restrict__ P1)
{
    const float* srcs[6] = { w0, w1, w2, w3, w4, w5 };
    int mtx = blockIdx.y;
    size_t base = (size_t)mtx * GG * DD;
    size_t i = (size_t)blockIdx.x * 256 + threadIdx.x;
    if (i >= (size_t)GG * DD) return;
    int n = (int)(i >> 9), k = (int)(i & 511);
    int g = n >> 9, d = n & 511;
    int c = ((d >> 2) << 4) + ((d & 3) << 1) + ((g >> 1) << 3) + (g & 1);
    fp16 a0, a1;
    split2(srcs[mtx][i], a0, a1);
    size_t o = base + ((size_t)c << 9) + k;
    P0[o] = a0; P1[o] = a1;
}

__global__ void permbias_all(const float* e1, const float* e2,
                             const float* d1, const float* d2,
                             float* __restrict__ bE, float* __restrict__ bD)
{
    int n = blockIdx.x * 256 + threadIdx.x;
    if (n >= GG) return;
    int g = n >> 9, d = n & 511;
    int c = ((d >> 2) << 4) + ((d & 3) << 1) + ((g >> 1) << 3) + (g & 1);
    bE[c] = e1[n] + e2[n];
    bD[c] = d1[n] + d2[n];
}

__global__ void table_all(const float* __restrict__ eemb, const float* __restrict__ eW,
                          const float* __restrict__ eb1, const float* __restrict__ eb2,
                          const float* __restrict__ demb, const float* __restrict__ dW,
                          const float* __restrict__ db1, const float* __restrict__ db2,
                          float* __restrict__ eT, float* __restrict__ dT)
{
    __shared__ float es[DD];
    int v = blockIdx.x;
    bool enc = v < DSRC;
    int vv = enc ? v : v - DSRC;
    const float* emb = enc ? eemb : demb;
    const float* W   = enc ? eW : dW;
    const float* b1  = enc ? eb1 : db1;
    const float* b2  = enc ? eb2 : db2;
    float* T         = enc ? eT : dT;
    int c = blockIdx.y * 128 + threadIdx.x;
    for (int i = threadIdx.x; i < DD; i += 128) es[i] = emb[(size_t)vv * DD + i];
    __syncthreads();
    int d = ((c >> 4) << 2) + ((c >> 1) & 3);
    int g = (((c >> 3) & 1) << 1) + (c & 1);
    int n = g * 512 + d;
    const float* w = W + (size_t)n * DD;
    float acc = b1[n] + b2[n];
    #pragma unroll 8
    for (int k = 0; k < DD; k++) acc = fmaf(es[k], w[k], acc);
    T[(size_t)vv * GG + c] = acc;
}

// ---------------- warp-reduced logits + argmax ----------------
__global__ void logits_argmax_kernel(const float* __restrict__ h,
                                     const float* __restrict__ W,
                                     const float* __restrict__ bias,
                                     float* __restrict__ out, int t,
                                     int* __restrict__ pred)
{
    __shared__ float hs[DD];
    __shared__ float lg[DTGT];
    int b = blockIdx.x;
    int tid = threadIdx.x, wid = tid >> 5, lane = tid & 31;
    for (int i = tid; i < DD; i += 256)
        hs[i] = h[(size_t)b * DD + i];
    __syncthreads();
    #pragma unroll
    for (int j = 0; j < 10; j++) {
        int n = wid * 10 + j;
        const float* w = W + (size_t)n * DD;
        float acc = 0.f;
        #pragma unroll
        for (int k = lane; k < DD; k += 32) acc = fmaf(hs[k], w[k], acc);
        #pragma unroll
        for (int o = 16; o; o >>= 1) acc += __shfl_xor_sync(0xFFFFFFFFu, acc, o);
        if (lane == 0) {
            float v = acc + bias[n];
            lg[n] = v;
            out[(size_t)b * (TTGT * DTGT) + t * DTGT + n] = v;
        }
    }
    __syncthreads();
    if (tid == 0) {
        float best = lg[0];
        int bi = 0;
        for (int i = 1; i < DTGT; i++)
            if (lg[i] > best) { best = lg[i]; bi = i; }
        pred[b] = bi;
    }
}

// ---------------- host orchestration ----------------
extern "C" void kernel_launch(void* const* d_in, const int* in_sizes, int n_in,
                              void* d_out, int out_size)
{
    const int*   src     = (const int*)  d_in[0];
    const int*   tgt     = (const int*)  d_in[1];
    const float* enc_emb = (const float*)d_in[2];
    const float* dec_emb = (const float*)d_in[3];
    const float* enc_Wih = (const float*)d_in[4];
    const float* enc_Whh = (const float*)d_in[5];
    const float* enc_bih = (const float*)d_in[6];
    const float* enc_bhh = (const float*)d_in[7];
    const float* dec_Wih = (const float*)d_in[8];
    const float* dec_Whh = (const float*)d_in[9];
    const float* dec_bih = (const float*)d_in[10];
    const float* dec_bhh = (const float*)d_in[11];
    const float* post_W  = (const float*)d_in[12];
    const float* post_b  = (const float*)d_in[13];
    float* out = (float*)d_out;

    cudaFuncSetAttribute(gemm_cell_dyn, cudaFuncAttributeMaxDynamicSharedMemorySize, SMEM_TOTAL_GEMM);

    fp16 *Wp0, *Wp1, *hp0, *hp1;
    float *cst, *hf, *encT, *decT, *biasE, *biasD;
    int* pred;
    cudaGetSymbolAddress((void**)&Wp0, g_Wp0);
    cudaGetSymbolAddress((void**)&Wp1, g_Wp1);
    cudaGetSymbolAddress((void**)&hp0, g_hp0);
    cudaGetSymbolAddress((void**)&hp1, g_hp1);
    cudaGetSymbolAddress((void**)&cst, g_c);
    cudaGetSymbolAddress((void**)&hf,  g_hf);
    cudaGetSymbolAddress((void**)&encT, g_encT);
    cudaGetSymbolAddress((void**)&decT, g_decT);
    cudaGetSymbolAddress((void**)&biasE, g_biasE);
    cudaGetSymbolAddress((void**)&biasD, g_biasD);
    cudaGetSymbolAddress((void**)&pred, g_pred);

    const size_t WSL = (size_t)GG * DD;
    const size_t HB  = (size_t)BB * DD;

    // layer-1 c state must start at zero (layer-0 c fully written by enc0_init)
    cudaMemsetAsync(cst + HB, 0, HB * sizeof(float), 0);

    // prep (3 kernels)
    permsplit_all<<<dim3((unsigned)((WSL + 255) / 256), 6), 256>>>(
        enc_Whh, enc_Wih + WSL, enc_Whh + WSL, dec_Whh, dec_Wih + WSL, dec_Whh + WSL, Wp0, Wp1);
    permbias_all<<<(GG + 255) / 256, 256>>>(enc_bih + GG, enc_bhh + GG,
                                            dec_bih + GG, dec_bhh + GG, biasE, biasD);
    table_all<<<dim3(DSRC + DTGT, GG / 128), 128>>>(
        enc_emb, enc_Wih, enc_bih, enc_bhh, dec_emb, dec_Wih, dec_bih, dec_bhh, encT, decT);

    int p0 = 0, p1 = 0;

    // ---- encoder t=0 via elementwise init (writes h0 parity 1, c0) ----
    enc0_init<<<(BB * DD + 255) / 256, 256>>>(src, encT, cst,
        hp0 + (0 * 2 + 1) * HB, hp1 + (0 * 2 + 1) * HB);
    p0 = 1;

    auto mk_l0_enc = [&](int t) {
        GArgs a = {};
        a.A10 = hp0 + (0 * 2 + p0) * HB;  a.A11 = hp1 + (0 * 2 + p0) * HB;
        a.W10 = Wp0 + 0 * WSL;            a.W11 = Wp1 + 0 * WSL;
        a.tb = encT; a.tok = src; a.tok_stride = TSRC; a.tok_off = t;
        a.cst = cst + 0 * HB; a.hf = nullptr;
        a.h0o = hp0 + (0 * 2 + (p0 ^ 1)) * HB;  a.h1o = hp1 + (0 * 2 + (p0 ^ 1)) * HB;
        a.x0o = nullptr; a.x1o = nullptr;      // Xs eliminated: l1 reads hp(l0) directly
        a.npass = 1; a.use_table = 1;
        return a;
    };
    auto mk_l1_enc = [&](int t) {
        GArgs a = {};
        // x operand = l0 output of step t = hp(l0, current p0)  (read-only share with l0[t+1])
        a.A10 = hp0 + (0 * 2 + p0) * HB;  a.A11 = hp1 + (0 * 2 + p0) * HB;
        a.W10 = Wp0 + 1 * WSL;            a.W11 = Wp1 + 1 * WSL;
        a.A20 = hp0 + (1 * 2 + p1) * HB;  a.A21 = hp1 + (1 * 2 + p1) * HB;
        a.W20 = Wp0 + 2 * WSL;            a.W21 = Wp1 + 2 * WSL;
        a.tb = biasE; a.tok = nullptr; a.tok_stride = 0; a.tok_off = 0;
        a.cst = cst + 1 * HB; a.hf = nullptr;
        a.h0o = hp0 + (1 * 2 + (p1 ^ 1)) * HB;  a.h1o = hp1 + (1 * 2 + (p1 ^ 1)) * HB;
        a.x0o = nullptr; a.x1o = nullptr;
        a.npass = (t == 0) ? 1 : 2; a.use_table = 0;
        return a;
    };
    auto mk_l0_dec0 = [&]() {   // decoder l0 at t=0 (tokens = tgt[:,0])
        GArgs a = {};
        a.A10 = hp0 + (0 * 2 + p0) * HB;  a.A11 = hp1 + (0 * 2 + p0) * HB;
        a.W10 = Wp0 + 3 * WSL;            a.W11 = Wp1 + 3 * WSL;
        a.tb = decT; a.tok = tgt; a.tok_stride = TTGT; a.tok_off = 0;
        a.cst = cst + 0 * HB; a.hf = nullptr;
        a.h0o = hp0 + (0 * 2 + (p0 ^ 1)) * HB;  a.h1o = hp1 + (0 * 2 + (p0 ^ 1)) * HB;
        a.x0o = nullptr; a.x1o = nullptr;
        a.npass = 1; a.use_table = 1;
        return a;
    };

    // ---- encoder: diagonal waves tau = 1..TSRC ----
    for (int tau = 1; tau <= TSRC; tau++) {
        if (tau < TSRC) {
            GArgs a0 = mk_l0_enc(tau);
            GArgs a1 = mk_l1_enc(tau - 1);     // reads hp(l0, p0) = l0 output of tau-1
            gemm_cell_dyn<<<dim3(GG / CTA_N, NROWB, 2), 256, SMEM_TOTAL_GEMM>>>(a0, a1);
            p0 ^= 1; p1 ^= 1;
        } else {
            // final wave: enc l1[31]  +  dec l0[0]  (independent, z=2)
            GArgs a0 = mk_l1_enc(tau - 1);
            GArgs a1 = mk_l0_dec0();
            gemm_cell_dyn<<<dim3(GG / CTA_N, NROWB, 2), 256, SMEM_TOTAL_GEMM>>>(a0, a1);
            p1 ^= 1; p0 ^= 1;
        }
    }

    // ---- decoder ----
    const dim3 gg(GG / CTA_N, NROWB, 1);
    for (int t = 0; t < TTGT; t++) {
        if (t > 0) {
            // layer 0: h-GEMM + table gather (pred tokens)
            GArgs a = {};
            a.A10 = hp0 + (0 * 2 + p0) * HB;  a.A11 = hp1 + (0 * 2 + p0) * HB;
            a.W10 = Wp0 + 3 * WSL;            a.W11 = Wp1 + 3 * WSL;
            a.tb = decT;
            a.tok = pred;  a.tok_stride = 1;  a.tok_off = 0;
            a.cst = cst + 0 * HB; a.hf = nullptr;
            a.h0o = hp0 + (0 * 2 + (p0 ^ 1)) * HB;  a.h1o = hp1 + (0 * 2 + (p0 ^ 1)) * HB;
            a.x0o = nullptr; a.x1o = nullptr;
            a.npass = 1; a.use_table = 1;
            gemm_cell_dyn<<<gg, 256, SMEM_TOTAL_GEMM>>>(a, a);
            p0 ^= 1;
        }
        // layer 1: dual GEMM (x = layer0 h of this step)
        GArgs b = {};
        b.A10 = hp0 + (0 * 2 + p0) * HB;  b.A11 = hp1 + (0 * 2 + p0) * HB;   // l0 output
        b.W10 = Wp0 + 4 * WSL;            b.W11 = Wp1 + 4 * WSL;
        b.A20 = hp0 + (1 * 2 + p1) * HB;  b.A21 = hp1 + (1 * 2 + p1) * HB;
        b.W20 = Wp0 + 5 * WSL;            b.W21 = Wp1 + 5 * WSL;
        b.tb = biasD; b.tok = nullptr; b.tok_stride = 0; b.tok_off = 0;
        b.cst = cst + 1 * HB; b.hf = hf;
        b.h0o = hp0 + (1 * 2 + (p1 ^ 1)) * HB;  b.h1o = hp1 + (1 * 2 + (p1 ^ 1)) * HB;
        b.x0o = nullptr; b.x1o = nullptr;
        b.npass = 2; b.use_table = 0;
        gemm_cell_dyn<<<gg, 256, SMEM_TOTAL_GEMM>>>(b, b);
        p1 ^= 1;

        logits_argmax_kernel<<<BB, 256>>>(hf, post_W, post_b, out, t, pred);
    }
}

// round 17
// speedup vs baseline: 1.0517x; 1.0055x over previous
#include <cuda_runtime.h>
#include <cuda_fp16.h>
#include <math.h>
#include <stdint.h>

// Problem constants
#define BB    2048
#define DD    512
#define GG    2048
#define TSRC  32
#define TTGT  32
#define DTGT  80
#define DSRC  100
#define NL    2

// GEMM tiling
#define CTA_M 128
#define CTA_N 128
#define NSTAGE 3
#define NROWB (BB / CTA_M)    // 16

#define STAGE_BYTES 32768
#define OFF_A0 0
#define OFF_A1 8192
#define OFF_B0 16384
#define OFF_B1 24576
#define BIAS_OFF (NSTAGE * STAGE_BYTES)          // 98304
#define SMEM_TOTAL_GEMM (BIAS_OFF + CTA_N * 4)   // 98816

#define SWZ(x) ((uint32_t)(x) ^ ((((uint32_t)(x)) >> 3) & 0x70))

typedef __half fp16;

// ---------------- persistent scratch ----------------
// permuted+split weights: [0]=encWhh0 [1]=encWih1 [2]=encWhh1 [3]=decWhh0 [4]=decWih1 [5]=decWhh1
__device__ __align__(256) fp16 g_Wp0[6][(size_t)GG * DD];
__device__ __align__(256) fp16 g_Wp1[6][(size_t)GG * DD];
__device__ __align__(256) fp16 g_hp0[NL][2][(size_t)BB * DD];
__device__ __align__(256) fp16 g_hp1[NL][2][(size_t)BB * DD];
__device__ float g_c[NL][(size_t)BB * DD];
__device__ float g_hf[(size_t)BB * DD];
__device__ float g_encT[(size_t)DSRC * GG];
__device__ float g_decT[(size_t)DTGT * GG];
__device__ float g_biasE[GG];
__device__ float g_biasD[GG];
__device__ int   g_pred[BB];

// ---------------- arg struct for runtime-dispatch GEMM ----------------
struct GArgs {
    const fp16 *A10, *A11, *W10, *W11;   // pass-0 operands
    const fp16 *A20, *A21, *W20, *W21;   // pass-1 operands
    const float* tb;                      // table (use_table) or permuted bias
    const int* tok; int tok_stride, tok_off;
    float* cst; float* hf;
    fp16 *h0o, *h1o, *x0o, *x1o;
    int npass; int use_table;
};

// ---------------- PTX helpers ----------------
__device__ __forceinline__ uint32_t smem_u32(const void* p) {
    uint32_t a;
    asm("{ .reg .u64 t; cvta.to.shared.u64 t, %1; cvt.u32.u64 %0, t; }" : "=r"(a) : "l"(p));
    return a;
}
__device__ __forceinline__ void cpasync16(uint32_t dst, const void* src) {
    asm volatile("cp.async.cg.shared.global [%0], [%1], 16;" :: "r"(dst), "l"(src));
}
#define CP_COMMIT()  asm volatile("cp.async.commit_group;" ::: "memory")
#define CP_WAIT(n)   asm volatile("cp.async.wait_group %0;" :: "n"(n) : "memory")

__device__ __forceinline__ void ldsm4(uint32_t* d, uint32_t addr) {
    asm volatile("ldmatrix.sync.aligned.m8n8.x4.shared.b16 {%0,%1,%2,%3}, [%4];"
        : "=r"(d[0]), "=r"(d[1]), "=r"(d[2]), "=r"(d[3]) : "r"(addr));
}
__device__ __forceinline__ void mma16816(float* c, const uint32_t* a, const uint32_t* b) {
    asm volatile(
        "mma.sync.aligned.m16n8k16.row.col.f32.f16.f16.f32 "
        "{%0,%1,%2,%3},{%4,%5,%6,%7},{%8,%9},{%0,%1,%2,%3};"
        : "+f"(c[0]), "+f"(c[1]), "+f"(c[2]), "+f"(c[3])
        : "r"(a[0]), "r"(a[1]), "r"(a[2]), "r"(a[3]), "r"(b[0]), "r"(b[1]));
}

__device__ __forceinline__ void split2(float x, fp16& a0, fp16& a1) {
    a0 = __float2half_rn(x);
    a1 = __float2half_rn(x - __half2float(a0));
}
__device__ __forceinline__ float sigf(float x) { return 1.f / (1.f + expf(-x)); }

// ---- fused GEMM + LSTM cell, runtime npass/use_table, grid.z dispatch ----
// (BYTE-IDENTICAL to the verified 9.39ms version — do not touch)
__global__ __launch_bounds__(256, 2)
void gemm_cell_dyn(GArgs a0, GArgs a1)
{
    const GArgs& a = (blockIdx.z == 1) ? a1 : a0;
    extern __shared__ char smem[];
    const uint32_t sb = smem_u32(smem);
    const int tid  = threadIdx.x;
    const int wid  = tid >> 5;
    const int lane = tid & 31;
    const int row0 = blockIdx.y * CTA_M;
    const int col0 = blockIdx.x * CTA_N;
    const int warp_m = (wid & 3) * 32;
    const int warp_n = (wid >> 2) * 64;
    const int KSTEPS = a.npass * 16;

    if (!a.use_table && tid < CTA_N)
        ((float*)(smem + BIAS_OFF))[tid] = a.tb[col0 + tid];

    auto load_stage = [&](int s, int slot) {
        const int pass = s >> 4;
        const size_t k0b = (size_t)(s & 15) * 64;
        const char* srcs[4];
        srcs[0] = (const char*)(pass ? a.A20 : a.A10) + (size_t)row0 * (DD * 2) + k0b;
        srcs[1] = (const char*)(pass ? a.A21 : a.A11) + (size_t)row0 * (DD * 2) + k0b;
        srcs[2] = (const char*)(pass ? a.W20 : a.W10) + (size_t)col0 * (DD * 2) + k0b;
        srcs[3] = (const char*)(pass ? a.W21 : a.W11) + (size_t)col0 * (DD * 2) + k0b;
        const uint32_t base = sb + slot * STAGE_BYTES;
        #pragma unroll
        for (int tile = 0; tile < 4; tile++) {
            #pragma unroll
            for (int hh = 0; hh < 2; hh++) {
                int j = hh * 256 + tid;
                int r = j >> 2, u = j & 3;
                cpasync16(base + tile * 8192 + SWZ(r * 64 + u * 16),
                          srcs[tile] + (size_t)r * (DD * 2) + u * 16);
            }
        }
        CP_COMMIT();
    };

    float acc[2][8][4];
    #pragma unroll
    for (int i = 0; i < 2; i++)
        #pragma unroll
        for (int j = 0; j < 8; j++)
            #pragma unroll
            for (int k = 0; k < 4; k++) acc[i][j][k] = 0.f;

    const int laA = lane & 15;
    const int luA = lane >> 4;
    const int laB = (lane & 7) + ((lane >> 4) << 3);
    const int luB = (lane >> 3) & 1;

    if (KSTEPS > 0) {
        load_stage(0, 0);
        load_stage(1, 1);

        #pragma unroll 1
        for (int s = 0; s < KSTEPS; s++) {
            if (s + 2 < KSTEPS) load_stage(s + 2, (s + 2) % NSTAGE);
            else CP_COMMIT();
            CP_WAIT(2);
            __syncthreads();

            const uint32_t stg = sb + (s % NSTAGE) * STAGE_BYTES;
            #pragma unroll
            for (int kh = 0; kh < 2; kh++) {
                uint32_t A[2][2][4];
                #pragma unroll
                for (int am = 0; am < 2; am++) {
                    uint32_t off = SWZ((warp_m + am * 16 + laA) * 64 + kh * 32 + luA * 16);
                    ldsm4(A[0][am], stg + OFF_A0 + off);
                    ldsm4(A[1][am], stg + OFF_A1 + off);
                }
                #pragma unroll
                for (int g = 0; g < 4; g++) {
                    uint32_t Bf[2][4];
                    uint32_t offb = SWZ((warp_n + g * 16 + laB) * 64 + kh * 32 + luB * 16);
                    ldsm4(Bf[0], stg + OFF_B0 + offb);
                    ldsm4(Bf[1], stg + OFF_B1 + offb);
                    #pragma unroll
                    for (int am = 0; am < 2; am++)
                        #pragma unroll
                        for (int sub = 0; sub < 2; sub++) {
                            float* c = acc[am][g * 2 + sub];
                            mma16816(c, A[0][am], &Bf[0][sub * 2]);
                            mma16816(c, A[0][am], &Bf[1][sub * 2]);
                            mma16816(c, A[1][am], &Bf[0][sub * 2]);
                        }
                }
            }
            __syncthreads();
        }
    } else {
        __syncthreads();   // bias/table visibility for npass==0 path
    }

    // ---- fused LSTM cell epilogue ----
    const float* bias_s = (const float*)(smem + BIAS_OFF);
    const int q = lane & 3, r = lane >> 2;
    const int dbase = ((col0 + warp_n) >> 4) * 4 + q;
    #pragma unroll
    for (int am = 0; am < 2; am++) {
        #pragma unroll
        for (int half = 0; half < 2; half++) {
            const int m = row0 + warp_m + am * 16 + r + half * 8;
            const float* trow = nullptr;
            if (a.use_table) {
                int tv = a.tok[(size_t)m * a.tok_stride + a.tok_off];
                trow = a.tb + (size_t)tv * GG + col0 + warp_n + q * 2;
            }
            #pragma unroll
            for (int g16 = 0; g16 < 4; g16++) {
                float* aIF = acc[am][g16 * 2 + 0];
                float* aGO = acc[am][g16 * 2 + 1];
                float gi = aIF[half * 2 + 0], gf = aIF[half * 2 + 1];
                float gg = aGO[half * 2 + 0], go = aGO[half * 2 + 1];
                if (a.use_table) {
                    float2 t0 = *(const float2*)(trow + g16 * 16);
                    float2 t1 = *(const float2*)(trow + g16 * 16 + 8);
                    gi += t0.x; gf += t0.y; gg += t1.x; go += t1.y;
                } else {
                    int cb = warp_n + g16 * 16 + q * 2;
                    gi += bias_s[cb]; gf += bias_s[cb + 1];
                    gg += bias_s[cb + 8]; go += bias_s[cb + 9];
                }
                float I = sigf(gi), F = sigf(gf), G = tanhf(gg), O = sigf(go);
                int d = dbase + g16 * 4;
                size_t idx = (size_t)m * DD + d;
                float cn = F * a.cst[idx] + I * G;
                float hn = O * tanhf(cn);
                a.cst[idx] = cn;
                if (a.hf) a.hf[idx] = hn;
                fp16 v0, v1; split2(hn, v0, v1);
                a.h0o[idx] = v0; a.h1o[idx] = v1;
                if (a.x0o) { a.x0o[idx] = v0; a.x1o[idx] = v1; }
            }
        }
    }
}

// ---------------- encoder t=0 init ----------------
__global__ void enc0_init(const int* __restrict__ src, const float* __restrict__ encT,
                          float* __restrict__ cst0,
                          fp16* __restrict__ h0o, fp16* __restrict__ h1o)
{
    int idx = blockIdx.x * 256 + threadIdx.x;
    if (idx >= BB * DD) return;
    int b = idx >> 9, d = idx & 511;
    int tok = src[b * TSRC + 0];
    const float* row = encT + (size_t)tok * GG;
    int cbase = ((d >> 2) << 4) + ((d & 3) << 1);
    float gi = row[cbase + 0];
    float gf = row[cbase + 1];
    float gg = row[cbase + 8];
    float go = row[cbase + 9];
    float I = sigf(gi), F = sigf(gf), G = tanhf(gg), O = sigf(go);
    float cn = F * 0.f + I * G;
    float hn = O * tanhf(cn);
    cst0[idx] = cn;
    fp16 v0, v1; split2(hn, v0, v1);
    h0o[idx] = v0; h1o[idx] = v1;
}

// ---------------- fused prep kernels ----------------
__global__ void permsplit_all(const float* w0, const float* w1, const float* w2,
                              const float* w3, const float* w4, const float* w5,
                              fp16* __restrict__ P0, fp16* __restrict__ P1)
{
    const float* srcs[6] = { w0, w1, w2, w3, w4, w5 };
    int mtx = blockIdx.y;
    size_t base = (size_t)mtx * GG * DD;
    size_t i = (size_t)blockIdx.x * 256 + threadIdx.x;
    if (i >= (size_t)GG * DD) return;
    int n = (int)(i >> 9), k = (int)(i & 511);
    int g = n >> 9, d = n & 511;
    int c = ((d >> 2) << 4) + ((d & 3) << 1) + ((g >> 1) << 3) + (g & 1);
    fp16 a0, a1;
    split2(srcs[mtx][i], a0, a1);
    size_t o = base + ((size_t)c << 9) + k;
    P0[o] = a0; P1[o] = a1;
}

__global__ void permbias_all(const float* e1, const float* e2,
                             const float* d1, const float* d2,
                             float* __restrict__ bE, float* __restrict__ bD)
{
    int n = blockIdx.x * 256 + threadIdx.x;
    if (n >= GG) return;
    int g = n >> 9, d = n & 511;
    int c = ((d >> 2) << 4) + ((d & 3) << 1) + ((g >> 1) << 3) + (g & 1);
    bE[c] = e1[n] + e2[n];
    bD[c] = d1[n] + d2[n];
}

__global__ void table_all(const float* __restrict__ eemb, const float* __restrict__ eW,
                          const float* __restrict__ eb1, const float* __restrict__ eb2,
                          const float* __restrict__ demb, const float* __restrict__ dW,
                          const float* __restrict__ db1, const float* __restrict__ db2,
                          float* __restrict__ eT, float* __restrict__ dT)
{
    __shared__ float es[DD];
    int v = blockIdx.x;
    bool enc = v < DSRC;
    int vv = enc ? v : v - DSRC;
    const float* emb = enc ? eemb : demb;
    const float* W   = enc ? eW : dW;
    const float* b1  = enc ? eb1 : db1;
    const float* b2  = enc ? eb2 : db2;
    float* T         = enc ? eT : dT;
    int c = blockIdx.y * 128 + threadIdx.x;
    for (int i = threadIdx.x; i < DD; i += 128) es[i] = emb[(size_t)vv * DD + i];
    __syncthreads();
    int d = ((c >> 4) << 2) + ((c >> 1) & 3);
    int g = (((c >> 3) & 1) << 1) + (c & 1);
    int n = g * 512 + d;
    const float* w = W + (size_t)n * DD;
    float acc = b1[n] + b2[n];
    #pragma unroll 8
    for (int k = 0; k < DD; k++) acc = fmaf(es[k], w[k], acc);
    T[(size_t)vv * GG + c] = acc;
}

// ---------------- warp-reduced logits + argmax ----------------
__global__ void logits_argmax_kernel(const float* __restrict__ h,
                                     const float* __restrict__ W,
                                     const float* __restrict__ bias,
                                     float* __restrict__ out, int t,
                                     int* __restrict__ pred)
{
    __shared__ float hs[DD];
    __shared__ float lg[DTGT];
    int b = blockIdx.x;
    int tid = threadIdx.x, wid = tid >> 5, lane = tid & 31;
    for (int i = tid; i < DD; i += 256)
        hs[i] = h[(size_t)b * DD + i];
    __syncthreads();
    #pragma unroll
    for (int j = 0; j < 10; j++) {
        int n = wid * 10 + j;
        const float* w = W + (size_t)n * DD;
        float acc = 0.f;
        #pragma unroll
        for (int k = lane; k < DD; k += 32) acc = fmaf(hs[k], w[k], acc);
        #pragma unroll
        for (int o = 16; o; o >>= 1) acc += __shfl_xor_sync(0xFFFFFFFFu, acc, o);
        if (lane == 0) {
            float v = acc + bias[n];
            lg[n] = v;
            out[(size_t)b * (TTGT * DTGT) + t * DTGT + n] = v;
        }
    }
    __syncthreads();
    if (tid == 0) {
        float best = lg[0];
        int bi = 0;
        for (int i = 1; i < DTGT; i++)
            if (lg[i] > best) { best = lg[i]; bi = i; }
        pred[b] = bi;
    }
}

// ---------------- host orchestration ----------------
extern "C" void kernel_launch(void* const* d_in, const int* in_sizes, int n_in,
                              void* d_out, int out_size)
{
    const int*   src     = (const int*)  d_in[0];
    const int*   tgt     = (const int*)  d_in[1];
    const float* enc_emb = (const float*)d_in[2];
    const float* dec_emb = (const float*)d_in[3];
    const float* enc_Wih = (const float*)d_in[4];
    const float* enc_Whh = (const float*)d_in[5];
    const float* enc_bih = (const float*)d_in[6];
    const float* enc_bhh = (const float*)d_in[7];
    const float* dec_Wih = (const float*)d_in[8];
    const float* dec_Whh = (const float*)d_in[9];
    const float* dec_bih = (const float*)d_in[10];
    const float* dec_bhh = (const float*)d_in[11];
    const float* post_W  = (const float*)d_in[12];
    const float* post_b  = (const float*)d_in[13];
    float* out = (float*)d_out;

    cudaFuncSetAttribute(gemm_cell_dyn, cudaFuncAttributeMaxDynamicSharedMemorySize, SMEM_TOTAL_GEMM);

    fp16 *Wp0, *Wp1, *hp0, *hp1;
    float *cst, *hf, *encT, *decT, *biasE, *biasD;
    int* pred;
    cudaGetSymbolAddress((void**)&Wp0, g_Wp0);
    cudaGetSymbolAddress((void**)&Wp1, g_Wp1);
    cudaGetSymbolAddress((void**)&hp0, g_hp0);
    cudaGetSymbolAddress((void**)&hp1, g_hp1);
    cudaGetSymbolAddress((void**)&cst, g_c);
    cudaGetSymbolAddress((void**)&hf,  g_hf);
    cudaGetSymbolAddress((void**)&encT, g_encT);
    cudaGetSymbolAddress((void**)&decT, g_decT);
    cudaGetSymbolAddress((void**)&biasE, g_biasE);
    cudaGetSymbolAddress((void**)&biasD, g_biasD);
    cudaGetSymbolAddress((void**)&pred, g_pred);

    const size_t WSL = (size_t)GG * DD;
    const size_t HB  = (size_t)BB * DD;

    // layer-1 c state must start at zero (layer-0 c fully written by enc0_init)
    cudaMemsetAsync(cst + HB, 0, HB * sizeof(float), 0);

    // prep (3 kernels)
    permsplit_all<<<dim3((unsigned)((WSL + 255) / 256), 6), 256>>>(
        enc_Whh, enc_Wih + WSL, enc_Whh + WSL, dec_Whh, dec_Wih + WSL, dec_Whh + WSL, Wp0, Wp1);
    permbias_all<<<(GG + 255) / 256, 256>>>(enc_bih + GG, enc_bhh + GG,
                                            dec_bih + GG, dec_bhh + GG, biasE, biasD);
    table_all<<<dim3(DSRC + DTGT, GG / 128), 128>>>(
        enc_emb, enc_Wih, enc_bih, enc_bhh, dec_emb, dec_Wih, dec_bih, dec_bhh, encT, decT);

    int p0 = 0, p1 = 0;

    // ---- encoder t=0 via elementwise init (writes h0 parity 1, c0) ----
    enc0_init<<<(BB * DD + 255) / 256, 256>>>(src, encT, cst,
        hp0 + (0 * 2 + 1) * HB, hp1 + (0 * 2 + 1) * HB);
    p0 = 1;

    auto mk_l0_enc = [&](int t) {
        GArgs a = {};
        a.A10 = hp0 + (0 * 2 + p0) * HB;  a.A11 = hp1 + (0 * 2 + p0) * HB;
        a.W10 = Wp0 + 0 * WSL;            a.W11 = Wp1 + 0 * WSL;
        a.tb = encT; a.tok = src; a.tok_stride = TSRC; a.tok_off = t;
        a.cst = cst + 0 * HB; a.hf = nullptr;
        a.h0o = hp0 + (0 * 2 + (p0 ^ 1)) * HB;  a.h1o = hp1 + (0 * 2 + (p0 ^ 1)) * HB;
        a.x0o = nullptr; a.x1o = nullptr;
        a.npass = 1; a.use_table = 1;
        return a;
    };
    auto mk_l1_enc = [&](int t) {
        GArgs a = {};
        // x operand = l0 output of step t = hp(l0, current p0)
        a.A10 = hp0 + (0 * 2 + p0) * HB;  a.A11 = hp1 + (0 * 2 + p0) * HB;
        a.W10 = Wp0 + 1 * WSL;            a.W11 = Wp1 + 1 * WSL;
        a.A20 = hp0 + (1 * 2 + p1) * HB;  a.A21 = hp1 + (1 * 2 + p1) * HB;
        a.W20 = Wp0 + 2 * WSL;            a.W21 = Wp1 + 2 * WSL;
        a.tb = biasE; a.tok = nullptr; a.tok_stride = 0; a.tok_off = 0;
        a.cst = cst + 1 * HB; a.hf = nullptr;
        a.h0o = hp0 + (1 * 2 + (p1 ^ 1)) * HB;  a.h1o = hp1 + (1 * 2 + (p1 ^ 1)) * HB;
        a.x0o = nullptr; a.x1o = nullptr;
        a.npass = (t == 0) ? 1 : 2; a.use_table = 0;
        return a;
    };
    auto mk_l0_dec0 = [&]() {   // decoder l0 at t=0 (tokens = tgt[:,0])
        GArgs a = {};
        a.A10 = hp0 + (0 * 2 + p0) * HB;  a.A11 = hp1 + (0 * 2 + p0) * HB;
        a.W10 = Wp0 + 3 * WSL;            a.W11 = Wp1 + 3 * WSL;
        a.tb = decT; a.tok = tgt; a.tok_stride = TTGT; a.tok_off = 0;
        a.cst = cst + 0 * HB; a.hf = nullptr;
        a.h0o = hp0 + (0 * 2 + (p0 ^ 1)) * HB;  a.h1o = hp1 + (0 * 2 + (p0 ^ 1)) * HB;
        a.x0o = nullptr; a.x1o = nullptr;
        a.npass = 1; a.use_table = 1;
        return a;
    };

    // ---- encoder: diagonal waves tau = 1..TSRC ----
    // Heavy (npass=2) job at z=0 so it rasterizes first: LPT scheduling keeps
    // the makespan at ~2 units instead of ~3.
    for (int tau = 1; tau <= TSRC; tau++) {
        if (tau < TSRC) {
            GArgs heavy = mk_l1_enc(tau - 1);   // npass 2 (1 at tau==1)
            GArgs light = mk_l0_enc(tau);       // npass 1
            gemm_cell_dyn<<<dim3(GG / CTA_N, NROWB, 2), 256, SMEM_TOTAL_GEMM>>>(heavy, light);
            p0 ^= 1; p1 ^= 1;
        } else {
            // final wave: enc l1[31] (heavy, z=0)  +  dec l0[0] (light, z=1)
            GArgs heavy = mk_l1_enc(tau - 1);
            GArgs light = mk_l0_dec0();
            gemm_cell_dyn<<<dim3(GG / CTA_N, NROWB, 2), 256, SMEM_TOTAL_GEMM>>>(heavy, light);
            p1 ^= 1; p0 ^= 1;
        }
    }

    // ---- decoder ----
    const dim3 gg(GG / CTA_N, NROWB, 1);
    for (int t = 0; t < TTGT; t++) {
        if (t > 0) {
            // layer 0: h-GEMM + table gather (pred tokens)
            GArgs a = {};
            a.A10 = hp0 + (0 * 2 + p0) * HB;  a.A11 = hp1 + (0 * 2 + p0) * HB;
            a.W10 = Wp0 + 3 * WSL;            a.W11 = Wp1 + 3 * WSL;
            a.tb = decT;
            a.tok = pred;  a.tok_stride = 1;  a.tok_off = 0;
            a.cst = cst + 0 * HB; a.hf = nullptr;
            a.h0o = hp0 + (0 * 2 + (p0 ^ 1)) * HB;  a.h1o = hp1 + (0 * 2 + (p0 ^ 1)) * HB;
            a.x0o = nullptr; a.x1o = nullptr;
            a.npass = 1; a.use_table = 1;
            gemm_cell_dyn<<<gg, 256, SMEM_TOTAL_GEMM>>>(a, a);
            p0 ^= 1;
        }
        // layer 1: dual GEMM (x = layer0 h of this step)
        GArgs b = {};
        b.A10 = hp0 + (0 * 2 + p0) * HB;  b.A11 = hp1 + (0 * 2 + p0) * HB;   // l0 output
        b.W10 = Wp0 + 4 * WSL;            b.W11 = Wp1 + 4 * WSL;
        b.A20 = hp0 + (1 * 2 + p1) * HB;  b.A21 = hp1 + (1 * 2 + p1) * HB;
        b.W20 = Wp0 + 5 * WSL;            b.W21 = Wp1 + 5 * WSL;
        b.tb = biasD; b.tok = nullptr; b.tok_stride = 0; b.tok_off = 0;
        b.cst = cst + 1 * HB; b.hf = hf;
        b.h0o = hp0 + (1 * 2 + (p1 ^ 1)) * HB;  b.h1o = hp1 + (1 * 2 + (p1 ^ 1)) * HB;
        b.x0o = nullptr; b.x1o = nullptr;
        b.npass = 2; b.use_table = 0;
        gemm_cell_dyn<<<gg, 256, SMEM_TOTAL_GEMM>>>(b, b);
        p1 ^= 1;

        logits_argmax_kernel<<<BB, 256>>>(hf, post_W, post_b, out, t, pred);
    }
}